// round 8
// baseline (speedup 1.0000x reference)
#include <cuda_runtime.h>
#include <cuda_bf16.h>
#include <stdint.h>
#include <math.h>

// ---------------- problem constants ----------------
#define BSZ   1024
#define OC    96
#define DW    200          // d_embd
#define HW    400          // 20*20
#define NENT  40000
#define NFC   115200       // 3*96*400
#define EPSB  1e-5f
#define SK1   18
#define CH1   (NFC / SK1)  // 6400
#define NK1   (CH1 / 32)   // 200 k-blocks of 32
#define KP2   224          // gemm2 K padded to mult of 32
#define NK2   (KP2 / 32)   // 7

// ---------------- device scratch ----------------
__device__ float g_x[BSZ * HW];
__device__ float g_bn0[2];
__device__ float g_bsum[3 * BSZ * OC];
__device__ float g_chsum[3 * OC];
__device__ float g_chsq[3 * OC];
__device__ float g_alpha[3 * OC];
__device__ float g_beta[3 * OC];
__device__ float g_scale[3 * BSZ * OC];
__device__ __align__(128) __nv_bfloat16 g_Ah[(long)BSZ * NFC];
__device__ __align__(128) __nv_bfloat16 g_Al[(long)BSZ * NFC];
__device__ __align__(128) __nv_bfloat16 g_Wh[(long)DW * NFC];
__device__ __align__(128) __nv_bfloat16 g_Wl[(long)DW * NFC];
__device__ float g_c1p[SK1 * BSZ * DW];
__device__ float g_c1[BSZ * DW];
__device__ __align__(128) __nv_bfloat16 g_zh[BSZ * KP2];
__device__ __align__(128) __nv_bfloat16 g_zl[BSZ * KP2];
__device__ __align__(128) __nv_bfloat16 g_nh[(long)NENT * KP2];
__device__ __align__(128) __nv_bfloat16 g_nl[(long)NENT * KP2];

// ---------------- PTX helpers ----------------
__device__ __forceinline__ void ldsm4(unsigned r[4], unsigned addr) {
    asm volatile("ldmatrix.sync.aligned.m8n8.x4.shared.b16 {%0,%1,%2,%3}, [%4];"
        : "=r"(r[0]), "=r"(r[1]), "=r"(r[2]), "=r"(r[3]) : "r"(addr));
}
__device__ __forceinline__ void mma_bf16(float* c, const unsigned* a,
                                         unsigned b0, unsigned b1) {
    asm volatile(
        "mma.sync.aligned.m16n8k16.row.col.f32.bf16.bf16.f32 "
        "{%0,%1,%2,%3}, {%4,%5,%6,%7}, {%8,%9}, {%0,%1,%2,%3};"
        : "+f"(c[0]), "+f"(c[1]), "+f"(c[2]), "+f"(c[3])
        : "r"(a[0]), "r"(a[1]), "r"(a[2]), "r"(a[3]), "r"(b0), "r"(b1));
}
__device__ __forceinline__ void cpa16(unsigned s, const void* g) {
    asm volatile("cp.async.ca.shared.global [%0], [%1], 16;" :: "r"(s), "l"(g));
}
__device__ __forceinline__ void cpa16z(unsigned s, const void* g, int srcsz) {
    asm volatile("cp.async.ca.shared.global [%0], [%1], 16, %2;"
                 :: "r"(s), "l"(g), "r"(srcsz));
}

// ---------------- kernel 0: zero atomics ----------------
__global__ void zero_stats() {
    int t = threadIdx.x;
    if (t < 2) g_bn0[t] = 0.f;
    if (t < 3 * OC) { g_chsum[t] = 0.f; g_chsq[t] = 0.f; }
}

// ---------------- kernel 1: gather + chequer + BN0 stats ----------------
__global__ void __launch_bounds__(128) gather_bn0(
    const float* __restrict__ n_feats, const float* __restrict__ r_feats,
    const int* __restrict__ sub, const int* __restrict__ rel)
{
    int b = blockIdx.x, t = threadIdx.x;
    int sb = sub[b], rb = rel[b];
    float s = 0.f, q = 0.f;
    for (int i = t; i < HW; i += 128) {
        float v = (i & 1) ? r_feats[rb * DW + (i >> 1)]
                          : n_feats[sb * DW + (i >> 1)];
        g_x[b * HW + i] = v;
        s += v; q += v * v;
    }
    __shared__ float ss[128], sq[128];
    ss[t] = s; sq[t] = q; __syncthreads();
    for (int st = 64; st > 0; st >>= 1) {
        if (t < st) { ss[t] += ss[t + st]; sq[t] += sq[t + st]; }
        __syncthreads();
    }
    if (t == 0) { atomicAdd(&g_bn0[0], ss[0]); atomicAdd(&g_bn0[1], sq[0]); }
}

// ---------------- conv helpers ----------------
__device__ __forceinline__ float conv_point(
    const float* __restrict__ xs, const float* __restrict__ fo,
    int brch, int h, int w)
{
    float acc = 0.f;
    if (brch == 0) {
        const float* xr = &xs[h * 20];
        acc = xr[w] * fo[2];
        if (w >= 2)  acc += xr[w - 2] * fo[0];
        if (w >= 1)  acc += xr[w - 1] * fo[1];
        if (w <= 18) acc += xr[w + 1] * fo[3];
        if (w <= 17) acc += xr[w + 2] * fo[4];
    } else if (brch == 1) {
        #pragma unroll
        for (int dh = 0; dh < 3; dh++) {
            int hh = h + dh - 1;
            if (hh < 0 || hh >= 20) continue;
            const float* xr = &xs[hh * 20];
            #pragma unroll
            for (int dw = 0; dw < 3; dw++) {
                int ww = w + dw - 1;
                if (ww >= 0 && ww < 20) acc += xr[ww] * fo[dh * 3 + dw];
            }
        }
    } else {
        #pragma unroll
        for (int dh = 0; dh < 5; dh++) {
            int hh = h + dh - 2;
            if (hh >= 0 && hh < 20) acc += xs[hh * 20 + w] * fo[dh];
        }
    }
    return acc;
}

// ---------------- kernel 2a: conv stats pass ----------------
__global__ void __launch_bounds__(384) conv3_stats(
    const float* __restrict__ f1, const float* __restrict__ f2,
    const float* __restrict__ f3, const int* __restrict__ rel,
    const float* __restrict__ bn0g, const float* __restrict__ bn0b)
{
    __shared__ float xs[HW];
    __shared__ float fs[OC * 9];
    int b = blockIdx.x, brch = blockIdx.y, t = threadIdx.x;

    float N0 = (float)BSZ * HW;
    float mean = g_bn0[0] / N0;
    float var  = g_bn0[1] / N0 - mean * mean;
    float a0 = bn0g[0] * rsqrtf(var + EPSB);
    float b0 = bn0b[0] - mean * a0;

    for (int i = t; i < HW; i += 384) xs[i] = g_x[b * HW + i] * a0 + b0;

    int rb = rel[b];
    int flen = (brch == 1) ? OC * 9 : OC * 5;
    int fstr = (brch == 1) ? 9 : 5;
    const float* fp = (brch == 0 ? f1 : (brch == 1 ? f2 : f3)) + (long)rb * flen;
    for (int i = t; i < flen; i += 384) fs[i] = fp[i];
    __syncthreads();

    int oc = t >> 2, q = t & 3;
    const float* fo = &fs[oc * fstr];
    float lsum = 0.f, lsq = 0.f;
    for (int p = q * 100; p < q * 100 + 100; p++) {
        int h = p / 20, w = p - h * 20;
        float acc = conv_point(xs, fo, brch, h, w);
        lsum += acc; lsq += acc * acc;
    }
    lsum += __shfl_down_sync(0xffffffffu, lsum, 2, 4);
    lsum += __shfl_down_sync(0xffffffffu, lsum, 1, 4);
    lsq  += __shfl_down_sync(0xffffffffu, lsq, 2, 4);
    lsq  += __shfl_down_sync(0xffffffffu, lsq, 1, 4);
    if (q == 0) {
        g_bsum[(brch * BSZ + b) * OC + oc] = lsum;
        atomicAdd(&g_chsum[brch * OC + oc], lsum);
        atomicAdd(&g_chsq[brch * OC + oc], lsq);
    }
}

// ---------------- kernel 3: BN affine ----------------
__global__ void bnaff(
    const float* __restrict__ g1, const float* __restrict__ b1,
    const float* __restrict__ g2, const float* __restrict__ b2,
    const float* __restrict__ g3, const float* __restrict__ b3)
{
    int i = threadIdx.x;
    if (i < 3 * OC) {
        int brch = i / OC, c = i - brch * OC;
        float N = (float)BSZ * HW;
        float mean = g_chsum[i] / N;
        float var  = g_chsq[i] / N - mean * mean;
        const float* g = brch == 0 ? g1 : (brch == 1 ? g2 : g3);
        const float* bb = brch == 0 ? b1 : (brch == 1 ? b2 : b3);
        float a = g[c] * rsqrtf(var + EPSB);
        g_alpha[i] = a;
        g_beta[i]  = bb[c] - mean * a;
    }
}

// ---------------- reductions ----------------
__device__ __forceinline__ float redsum128(float v, float* sm) {
    int t = threadIdx.x;
    sm[t] = v; __syncthreads();
    for (int s = 64; s > 0; s >>= 1) {
        if (t < s) sm[t] += sm[t + s];
        __syncthreads();
    }
    float r = sm[0]; __syncthreads();
    return r;
}
__device__ __forceinline__ float redmax128(float v, float* sm) {
    int t = threadIdx.x;
    sm[t] = v; __syncthreads();
    for (int s = 64; s > 0; s >>= 1) {
        if (t < s) sm[t] = fmaxf(sm[t], sm[t + s]);
        __syncthreads();
    }
    float r = sm[0]; __syncthreads();
    return r;
}

// ---------------- kernel 4: SE + ATT gates ----------------
__global__ void __launch_bounds__(128) gates(
    const float* __restrict__ s1w1, const float* __restrict__ s1w2,
    const float* __restrict__ s2w1, const float* __restrict__ s2w2,
    const float* __restrict__ s3w1, const float* __restrict__ s3w2,
    const float* __restrict__ aw1, const float* __restrict__ aw2)
{
    __shared__ float sm[128];
    int b = blockIdx.x, t = threadIdx.x;
    bool act = t < OC;
    int oc = act ? t : 0;

    const float* w1s[3] = {s1w1, s2w1, s3w1};
    const float* w2s[3] = {s1w2, s2w2, s3w2};

    float pool[3], seg[3];
    #pragma unroll
    for (int br = 0; br < 3; br++) {
        float p = fmaf(g_alpha[br * OC + oc],
                       g_bsum[(br * BSZ + b) * OC + oc] * (1.f / HW),
                       g_beta[br * OC + oc]);
        pool[br] = act ? p : 0.f;
    }
    #pragma unroll
    for (int br = 0; br < 3; br++) {
        float h0 = redsum128(act ? pool[br] * w1s[br][oc] : 0.f, sm);
        float h1 = redsum128(act ? pool[br] * w1s[br][OC + oc] : 0.f, sm);
        h0 = fmaxf(h0, 0.f); h1 = fmaxf(h1, 0.f);
        float lg = h0 * w2s[br][oc * 2] + h1 * w2s[br][oc * 2 + 1];
        seg[br] = 1.f / (1.f + expf(-lg));
    }
    float attp = seg[0] * pool[0] + seg[1] * pool[1] + seg[2] * pool[2];
    float a0 = fmaxf(redsum128(act ? attp * aw1[oc] : 0.f, sm), 0.f);
    float a1 = fmaxf(redsum128(act ? attp * aw1[OC + oc] : 0.f, sm), 0.f);

    float l[3], mx = -1e30f;
    #pragma unroll
    for (int br = 0; br < 3; br++) {
        l[br] = act ? (a0 * aw2[(br * OC + oc) * 2] + a1 * aw2[(br * OC + oc) * 2 + 1])
                    : -1e30f;
        mx = fmaxf(mx, l[br]);
    }
    float gm = redmax128(mx, sm);
    float e[3], le = 0.f;
    #pragma unroll
    for (int br = 0; br < 3; br++) { e[br] = expf(l[br] - gm); le += e[br]; }
    float S = redsum128(le, sm);
    if (act) {
        #pragma unroll
        for (int br = 0; br < 3; br++)
            g_scale[(br * BSZ + b) * OC + oc] = seg[br] * e[br] / S;
    }
}

// ---------------- kernel 2b: conv recompute + gate + relu -> bf16 hi/lo ----------------
__global__ void __launch_bounds__(384) conv3_fused(
    const float* __restrict__ f1, const float* __restrict__ f2,
    const float* __restrict__ f3, const int* __restrict__ rel,
    const float* __restrict__ bn0g, const float* __restrict__ bn0b)
{
    __shared__ float xs[HW];
    __shared__ float fs[OC * 9];
    __shared__ float sA[OC], sBt[OC], sS[OC];
    int b = blockIdx.x, brch = blockIdx.y, t = threadIdx.x;

    float N0 = (float)BSZ * HW;
    float mean = g_bn0[0] / N0;
    float var  = g_bn0[1] / N0 - mean * mean;
    float a0 = bn0g[0] * rsqrtf(var + EPSB);
    float b0 = bn0b[0] - mean * a0;

    for (int i = t; i < HW; i += 384) xs[i] = g_x[b * HW + i] * a0 + b0;

    int rb = rel[b];
    int flen = (brch == 1) ? OC * 9 : OC * 5;
    int fstr = (brch == 1) ? 9 : 5;
    const float* fp = (brch == 0 ? f1 : (brch == 1 ? f2 : f3)) + (long)rb * flen;
    for (int i = t; i < flen; i += 384) fs[i] = fp[i];
    if (t < OC) {
        sA[t]  = g_alpha[brch * OC + t];
        sBt[t] = g_beta[brch * OC + t];
        sS[t]  = g_scale[(brch * BSZ + b) * OC + t];
    }
    __syncthreads();

    long obase = (long)b * NFC + (long)brch * (OC * HW);
    for (int i = t; i < OC * HW; i += 384) {
        int oc = i / HW, p = i - oc * HW;
        int h = p / 20, w = p - h * 20;
        float acc = conv_point(xs, &fs[oc * fstr], brch, h, w);
        float v = fmaxf(fmaf(sA[oc], acc, sBt[oc]) * sS[oc], 0.f);
        __nv_bfloat16 hh = __float2bfloat16(v);
        g_Ah[obase + i] = hh;
        g_Al[obase + i] = __float2bfloat16(v - __bfloat162float(hh));
    }
}

// ---------------- split kernels (vectorized) ----------------
__global__ void __launch_bounds__(256) splitW(const float* __restrict__ w) {
    long i4 = (long)blockIdx.x * 256 + threadIdx.x;   // 22500 blocks x 4 floats
    float4 v = ((const float4*)w)[i4];
    __nv_bfloat16 h0 = __float2bfloat16(v.x), h1 = __float2bfloat16(v.y);
    __nv_bfloat16 h2 = __float2bfloat16(v.z), h3 = __float2bfloat16(v.w);
    __nv_bfloat162 hh0, hh1, ll0, ll1;
    hh0.x = h0; hh0.y = h1; hh1.x = h2; hh1.y = h3;
    ll0.x = __float2bfloat16(v.x - __bfloat162float(h0));
    ll0.y = __float2bfloat16(v.y - __bfloat162float(h1));
    ll1.x = __float2bfloat16(v.z - __bfloat162float(h2));
    ll1.y = __float2bfloat16(v.w - __bfloat162float(h3));
    ((__nv_bfloat162*)g_Wh)[i4 * 2]     = hh0;
    ((__nv_bfloat162*)g_Wh)[i4 * 2 + 1] = hh1;
    ((__nv_bfloat162*)g_Wl)[i4 * 2]     = ll0;
    ((__nv_bfloat162*)g_Wl)[i4 * 2 + 1] = ll1;
}

__global__ void __launch_bounds__(256) splitN(const float* __restrict__ nf) {
    long t = (long)blockIdx.x * 256 + threadIdx.x;   // 35000 blocks: 40000*224
    int e = (int)(t / KP2), j = (int)(t - (long)e * KP2);
    float v = (j < DW) ? nf[(long)e * DW + j] : 0.f;
    __nv_bfloat16 h = __float2bfloat16(v);
    g_nh[t] = h;
    g_nl[t] = __float2bfloat16(v - __bfloat162float(h));
}

// ---------------- HMMA bf16x3 GEMM: 128x128 tile, kstep32, 3 stages, 1 barrier/iter
// stage (32KB) = sub0[Ah 4K][Al 4K][Bh 4K][Bl 4K] + sub1[same]
#define STG32 32768u
__device__ __forceinline__ void gemm_hmma(
    const __nv_bfloat16* __restrict__ Ah, const __nv_bfloat16* __restrict__ Al, long lda,
    const __nv_bfloat16* __restrict__ Bh, const __nv_bfloat16* __restrict__ Bl, long ldb,
    float* __restrict__ C, long ldc, int Nn,
    int m0, int n0, long k0, int nk, const float* __restrict__ bias)
{
    extern __shared__ __align__(128) char smem[];
    unsigned sb = (unsigned)__cvta_generic_to_shared(smem);
    int tid = threadIdx.x, lane = tid & 31, wid = tid >> 5;
    int wm = (wid >> 2) * 64, wn = (wid & 3) * 32;

    float acc[4][4][4];
    #pragma unroll
    for (int i = 0; i < 4; i++)
        #pragma unroll
        for (int j = 0; j < 4; j++)
            #pragma unroll
            for (int k = 0; k < 4; k++) acc[i][j][k] = 0.f;

    // 2048 chunks of 16B per stage; 8 per thread
    #define ISSUE(stg_, kb_) do {                                              \
        unsigned s0_ = sb + (unsigned)(stg_) * STG32;                          \
        long kk_ = k0 + (long)(kb_) * 32;                                      \
        _Pragma("unroll")                                                      \
        for (int ii = 0; ii < 8; ii++) {                                       \
            int i_ = tid + ii * 256;                                           \
            int sub_ = i_ >> 10, rem_ = i_ & 1023;                             \
            int pl_ = rem_ >> 8, r_ = (rem_ >> 1) & 127, c_ = rem_ & 1;        \
            unsigned sw_ = s0_ + (unsigned)sub_ * 16384u + (unsigned)pl_ * 4096u \
                + (unsigned)r_ * 32u + (unsigned)((c_ ^ ((r_ >> 2) & 1)) * 16);\
            long gk_ = kk_ + sub_ * 16 + c_ * 8;                               \
            if (pl_ == 0)      cpa16(sw_, Ah + (long)(m0 + r_) * lda + gk_);   \
            else if (pl_ == 1) cpa16(sw_, Al + (long)(m0 + r_) * lda + gk_);   \
            else {                                                             \
                int ok_ = ((n0 + r_) < Nn) ? 16 : 0;                           \
                const __nv_bfloat16* P_ = (pl_ == 2) ? Bh : Bl;                \
                cpa16z(sw_, P_ + (long)(n0 + r_) * ldb + gk_, ok_);            \
            }                                                                  \
        }                                                                      \
        asm volatile("cp.async.commit_group;" ::: "memory");                   \
    } while (0)

    // per-warp ldmatrix offsets relative to sub-block base
    int cbit = lane >> 4;
    unsigned aoff[4], boff[2];
    #pragma unroll
    for (int mt = 0; mt < 4; mt++) {
        int r = wm + mt * 16 + (lane & 15);
        aoff[mt] = (unsigned)r * 32u + (unsigned)((cbit ^ ((r >> 2) & 1)) * 16);
    }
    #pragma unroll
    for (int j = 0; j < 2; j++) {
        int r = wn + j * 16 + (lane & 15);
        boff[j] = 8192u + (unsigned)r * 32u
                + (unsigned)((cbit ^ ((r >> 2) & 1)) * 16);
    }

    ISSUE(0, 0);
    ISSUE(1, 1);

    for (int kb = 0; kb < nk; kb++) {
        int st = kb % 3;
        if (kb + 1 < nk)
            asm volatile("cp.async.wait_group 1;" ::: "memory");
        else
            asm volatile("cp.async.wait_group 0;" ::: "memory");
        __syncthreads();               // single barrier per 32-k iteration
        if (kb + 2 < nk) ISSUE((kb + 2) % 3, kb + 2);

        unsigned s0 = sb + (unsigned)st * STG32;
        unsigned s1 = s0 + 16384u;

        unsigned bh0[2][4], bl0[2][4], ah0[4][4], al0[4][4];
        unsigned bh1[2][4], bl1[2][4], ah1[4][4], al1[4][4];
        #pragma unroll
        for (int j = 0; j < 2; j++) {
            ldsm4(bh0[j], s0 + boff[j]);
            ldsm4(bl0[j], s0 + boff[j] + 4096u);
        }
        #pragma unroll
        for (int mt = 0; mt < 4; mt++) {
            ldsm4(ah0[mt], s0 + aoff[mt]);
            ldsm4(al0[mt], s0 + aoff[mt] + 4096u);
        }
        #pragma unroll
        for (int j = 0; j < 2; j++) {
            ldsm4(bh1[j], s1 + boff[j]);
            ldsm4(bl1[j], s1 + boff[j] + 4096u);
        }
        #pragma unroll
        for (int mt = 0; mt < 4; mt++) {
            ldsm4(ah1[mt], s1 + aoff[mt]);
            ldsm4(al1[mt], s1 + aoff[mt] + 4096u);
        }

        #pragma unroll
        for (int mt = 0; mt < 4; mt++)
            #pragma unroll
            for (int j = 0; j < 2; j++) {
                mma_bf16(acc[mt][2*j],   ah0[mt], bh0[j][0], bh0[j][2]);
                mma_bf16(acc[mt][2*j],   ah0[mt], bl0[j][0], bl0[j][2]);
                mma_bf16(acc[mt][2*j],   al0[mt], bh0[j][0], bh0[j][2]);
                mma_bf16(acc[mt][2*j+1], ah0[mt], bh0[j][1], bh0[j][3]);
                mma_bf16(acc[mt][2*j+1], ah0[mt], bl0[j][1], bl0[j][3]);
                mma_bf16(acc[mt][2*j+1], al0[mt], bh0[j][1], bh0[j][3]);
            }
        #pragma unroll
        for (int mt = 0; mt < 4; mt++)
            #pragma unroll
            for (int j = 0; j < 2; j++) {
                mma_bf16(acc[mt][2*j],   ah1[mt], bh1[j][0], bh1[j][2]);
                mma_bf16(acc[mt][2*j],   ah1[mt], bl1[j][0], bl1[j][2]);
                mma_bf16(acc[mt][2*j],   al1[mt], bh1[j][0], bh1[j][2]);
                mma_bf16(acc[mt][2*j+1], ah1[mt], bh1[j][1], bh1[j][3]);
                mma_bf16(acc[mt][2*j+1], ah1[mt], bl1[j][1], bl1[j][3]);
                mma_bf16(acc[mt][2*j+1], al1[mt], bh1[j][1], bh1[j][3]);
            }
    }
    #undef ISSUE

    #pragma unroll
    for (int mt = 0; mt < 4; mt++) {
        #pragma unroll
        for (int nt = 0; nt < 4; nt++) {
            int rr = m0 + wm + mt * 16 + (lane >> 2);
            int cc = n0 + wn + nt * 8 + (lane & 3) * 2;
            if (cc < Nn) {
                float bv0 = bias ? bias[cc] : 0.f;
                float bv1 = bias ? bias[cc + 1] : 0.f;
                C[(long)rr * ldc + cc]           = acc[mt][nt][0] + bv0;
                C[(long)rr * ldc + cc + 1]       = acc[mt][nt][1] + bv1;
                C[(long)(rr + 8) * ldc + cc]     = acc[mt][nt][2] + bv0;
                C[(long)(rr + 8) * ldc + cc + 1] = acc[mt][nt][3] + bv1;
            }
        }
    }
}

__global__ void __launch_bounds__(256) gemm1_k() {
    gemm_hmma(g_Ah, g_Al, NFC, g_Wh, g_Wl, NFC,
              g_c1p + (long)blockIdx.z * (BSZ * DW), DW, DW,
              blockIdx.y * 128, blockIdx.x * 128,
              (long)blockIdx.z * CH1, NK1, nullptr);
}

__global__ void __launch_bounds__(256) gemm2_k(
    const float* __restrict__ biasb, float* __restrict__ out) {
    gemm_hmma(g_zh, g_zl, KP2, g_nh, g_nl, KP2,
              out, NENT, NENT,
              blockIdx.y * 128, blockIdx.x * 128, 0, NK2, biasb);
}

// ---------------- kernel 6: split-K reduce + fc bias ----------------
__global__ void __launch_bounds__(256) reduce_c1(const float* __restrict__ fcb) {
    int idx = blockIdx.x * 256 + threadIdx.x;     // 800*256 == 204800
    float s = 0.f;
    #pragma unroll
    for (int z = 0; z < SK1; z++) s += g_c1p[z * (BSZ * DW) + idx];
    g_c1[idx] = s + fcb[idx % DW];
}

// ---------------- kernel 7: BN1d + ReLU -> bf16 hi/lo (padded to KP2) ----------------
__global__ void __launch_bounds__(256) bn2_relu(
    const float* __restrict__ g2, const float* __restrict__ b2) {
    int d = blockIdx.x, t = threadIdx.x;          // d in [0,KP2)
    if (d >= DW) {
        for (int b = t; b < BSZ; b += 256) {
            g_zh[b * KP2 + d] = __float2bfloat16(0.f);
            g_zl[b * KP2 + d] = __float2bfloat16(0.f);
        }
        return;
    }
    float s = 0.f, q = 0.f;
    for (int b = t; b < BSZ; b += 256) {
        float v = g_c1[b * DW + d];
        s += v; q += v * v;
    }
    __shared__ float ss[256], sq[256];
    ss[t] = s; sq[t] = q; __syncthreads();
    for (int st = 128; st > 0; st >>= 1) {
        if (t < st) { ss[t] += ss[t + st]; sq[t] += sq[t + st]; }
        __syncthreads();
    }
    float mean = ss[0] / BSZ;
    float var  = sq[0] / BSZ - mean * mean;
    float a = g2[d] * rsqrtf(var + EPSB);
    float bb = b2[d] - mean * a;
    for (int b = t; b < BSZ; b += 256) {
        float v = fmaxf(fmaf(a, g_c1[b * DW + d], bb), 0.f);
        __nv_bfloat16 h = __float2bfloat16(v);
        g_zh[b * KP2 + d] = h;
        g_zl[b * KP2 + d] = __float2bfloat16(v - __bfloat162float(h));
    }
}

// ---------------- launch ----------------
extern "C" void kernel_launch(void* const* d_in, const int* in_sizes, int n_in,
                              void* d_out, int out_size) {
    const float* n_feats = (const float*)d_in[0];
    const float* r_feats = (const float*)d_in[1];
    const float* filt1   = (const float*)d_in[2];
    const float* filt2   = (const float*)d_in[3];
    const float* filt3   = (const float*)d_in[4];
    const float* bn0_g   = (const float*)d_in[5];
    const float* bn0_b   = (const float*)d_in[6];
    const float* bn1_g   = (const float*)d_in[7];
    const float* bn1_b   = (const float*)d_in[8];
    const float* bn2c_g  = (const float*)d_in[9];
    const float* bn2c_b  = (const float*)d_in[10];
    const float* bn3c_g  = (const float*)d_in[11];
    const float* bn3c_b  = (const float*)d_in[12];
    const float* se1_w1  = (const float*)d_in[13];
    const float* se1_w2  = (const float*)d_in[14];
    const float* se2_w1  = (const float*)d_in[15];
    const float* se2_w2  = (const float*)d_in[16];
    const float* se3_w1  = (const float*)d_in[17];
    const float* se3_w2  = (const float*)d_in[18];
    const float* att_w1  = (const float*)d_in[19];
    const float* att_w2  = (const float*)d_in[20];
    const float* fc_w    = (const float*)d_in[21];
    const float* fc_b    = (const float*)d_in[22];
    const float* bn2_g   = (const float*)d_in[23];
    const float* bn2_b   = (const float*)d_in[24];
    const float* bias_b  = (const float*)d_in[25];
    const int*   sub     = (const int*)d_in[26];
    const int*   rel     = (const int*)d_in[27];

    const int smem = 3 * (int)STG32;   // 98304
    cudaFuncSetAttribute(gemm1_k, cudaFuncAttributeMaxDynamicSharedMemorySize, smem);
    cudaFuncSetAttribute(gemm2_k, cudaFuncAttributeMaxDynamicSharedMemorySize, smem);

    zero_stats<<<1, 3 * OC>>>();
    splitW<<<22500, 256>>>(fc_w);
    splitN<<<35000, 256>>>(n_feats);
    gather_bn0<<<BSZ, 128>>>(n_feats, r_feats, sub, rel);
    conv3_stats<<<dim3(BSZ, 3), 384>>>(filt1, filt2, filt3, rel, bn0_g, bn0_b);
    bnaff<<<1, 3 * OC>>>(bn1_g, bn1_b, bn2c_g, bn2c_b, bn3c_g, bn3c_b);
    gates<<<BSZ, 128>>>(se1_w1, se1_w2, se2_w1, se2_w2, se3_w1, se3_w2,
                        att_w1, att_w2);
    conv3_fused<<<dim3(BSZ, 3), 384>>>(filt1, filt2, filt3, rel, bn0_g, bn0_b);
    gemm1_k<<<dim3(2, BSZ / 128, SK1), 256, smem>>>();
    reduce_c1<<<800, 256>>>(fc_b);
    bn2_relu<<<KP2, 256>>>(bn2_g, bn2_b);
    gemm2_k<<<dim3((NENT + 127) / 128, BSZ / 128), 256, smem>>>(bias_b,
                                                               (float*)d_out);
}

// round 9
// speedup vs baseline: 1.3290x; 1.3290x over previous
#include <cuda_runtime.h>
#include <cuda_bf16.h>
#include <cuda_fp16.h>
#include <stdint.h>
#include <math.h>

// ---------------- problem constants ----------------
#define BSZ   1024
#define OC    96
#define DW    200          // d_embd
#define HW    400          // 20*20
#define NENT  40000
#define NFC   115200       // 3*96*400
#define EPSB  1e-5f
#define SK1   18
#define CH1   (NFC / SK1)  // 6400
#define NK1   (CH1 / 16)   // 400 k-steps of 16
#define KP2   208          // gemm2 K padded to mult of 16
#define NK2   (KP2 / 16)   // 13

// ---------------- device scratch ----------------
__device__ float g_x[BSZ * HW];
__device__ float g_bn0[2];
__device__ float g_bsum[3 * BSZ * OC];
__device__ float g_chsum[3 * OC];
__device__ float g_chsq[3 * OC];
__device__ float g_alpha[3 * OC];
__device__ float g_beta[3 * OC];
__device__ float g_scale[3 * BSZ * OC];
__device__ __align__(128) __half g_A [(long)BSZ * NFC];   // activations, single fp16
__device__ __align__(128) __half g_Wh[(long)DW * NFC];    // fc weight hi
__device__ __align__(128) __half g_Wl[(long)DW * NFC];    // fc weight lo
__device__ float g_c1p[SK1 * BSZ * DW];
__device__ float g_c1[BSZ * DW];
__device__ __align__(128) __half g_z [BSZ * KP2];         // BN2 output, single fp16
__device__ __align__(128) __half g_nh[(long)NENT * KP2];  // n_feats hi
__device__ __align__(128) __half g_nl[(long)NENT * KP2];  // n_feats lo

// ---------------- PTX helpers ----------------
__device__ __forceinline__ void ldsm4(unsigned r[4], unsigned addr) {
    asm volatile("ldmatrix.sync.aligned.m8n8.x4.shared.b16 {%0,%1,%2,%3}, [%4];"
        : "=r"(r[0]), "=r"(r[1]), "=r"(r[2]), "=r"(r[3]) : "r"(addr));
}
__device__ __forceinline__ void mma_fp16(float* c, const unsigned* a,
                                         unsigned b0, unsigned b1) {
    asm volatile(
        "mma.sync.aligned.m16n8k16.row.col.f32.f16.f16.f32 "
        "{%0,%1,%2,%3}, {%4,%5,%6,%7}, {%8,%9}, {%0,%1,%2,%3};"
        : "+f"(c[0]), "+f"(c[1]), "+f"(c[2]), "+f"(c[3])
        : "r"(a[0]), "r"(a[1]), "r"(a[2]), "r"(a[3]), "r"(b0), "r"(b1));
}
__device__ __forceinline__ void cpa16(unsigned s, const void* g) {
    asm volatile("cp.async.ca.shared.global [%0], [%1], 16;" :: "r"(s), "l"(g));
}
__device__ __forceinline__ void cpa16z(unsigned s, const void* g, int srcsz) {
    asm volatile("cp.async.ca.shared.global [%0], [%1], 16, %2;"
                 :: "r"(s), "l"(g), "r"(srcsz));
}

// ---------------- kernel 0: zero atomics ----------------
__global__ void zero_stats() {
    int t = threadIdx.x;
    if (t < 2) g_bn0[t] = 0.f;
    if (t < 3 * OC) { g_chsum[t] = 0.f; g_chsq[t] = 0.f; }
}

// ---------------- kernel 1: gather + chequer + BN0 stats ----------------
__global__ void __launch_bounds__(128) gather_bn0(
    const float* __restrict__ n_feats, const float* __restrict__ r_feats,
    const int* __restrict__ sub, const int* __restrict__ rel)
{
    int b = blockIdx.x, t = threadIdx.x;
    int sb = sub[b], rb = rel[b];
    float s = 0.f, q = 0.f;
    for (int i = t; i < HW; i += 128) {
        float v = (i & 1) ? r_feats[rb * DW + (i >> 1)]
                          : n_feats[sb * DW + (i >> 1)];
        g_x[b * HW + i] = v;
        s += v; q += v * v;
    }
    __shared__ float ss[128], sq[128];
    ss[t] = s; sq[t] = q; __syncthreads();
    for (int st = 64; st > 0; st >>= 1) {
        if (t < st) { ss[t] += ss[t + st]; sq[t] += sq[t + st]; }
        __syncthreads();
    }
    if (t == 0) { atomicAdd(&g_bn0[0], ss[0]); atomicAdd(&g_bn0[1], sq[0]); }
}

// ---------------- conv helpers ----------------
__device__ __forceinline__ float conv_point(
    const float* __restrict__ xs, const float* __restrict__ fo,
    int brch, int h, int w)
{
    float acc = 0.f;
    if (brch == 0) {
        const float* xr = &xs[h * 20];
        acc = xr[w] * fo[2];
        if (w >= 2)  acc += xr[w - 2] * fo[0];
        if (w >= 1)  acc += xr[w - 1] * fo[1];
        if (w <= 18) acc += xr[w + 1] * fo[3];
        if (w <= 17) acc += xr[w + 2] * fo[4];
    } else if (brch == 1) {
        #pragma unroll
        for (int dh = 0; dh < 3; dh++) {
            int hh = h + dh - 1;
            if (hh < 0 || hh >= 20) continue;
            const float* xr = &xs[hh * 20];
            #pragma unroll
            for (int dw = 0; dw < 3; dw++) {
                int ww = w + dw - 1;
                if (ww >= 0 && ww < 20) acc += xr[ww] * fo[dh * 3 + dw];
            }
        }
    } else {
        #pragma unroll
        for (int dh = 0; dh < 5; dh++) {
            int hh = h + dh - 2;
            if (hh >= 0 && hh < 20) acc += xs[hh * 20 + w] * fo[dh];
        }
    }
    return acc;
}

// ---------------- kernel 2a: conv stats pass ----------------
__global__ void __launch_bounds__(384) conv3_stats(
    const float* __restrict__ f1, const float* __restrict__ f2,
    const float* __restrict__ f3, const int* __restrict__ rel,
    const float* __restrict__ bn0g, const float* __restrict__ bn0b)
{
    __shared__ float xs[HW];
    __shared__ float fs[OC * 9];
    int b = blockIdx.x, brch = blockIdx.y, t = threadIdx.x;

    float N0 = (float)BSZ * HW;
    float mean = g_bn0[0] / N0;
    float var  = g_bn0[1] / N0 - mean * mean;
    float a0 = bn0g[0] * rsqrtf(var + EPSB);
    float b0 = bn0b[0] - mean * a0;

    for (int i = t; i < HW; i += 384) xs[i] = g_x[b * HW + i] * a0 + b0;

    int rb = rel[b];
    int flen = (brch == 1) ? OC * 9 : OC * 5;
    int fstr = (brch == 1) ? 9 : 5;
    const float* fp = (brch == 0 ? f1 : (brch == 1 ? f2 : f3)) + (long)rb * flen;
    for (int i = t; i < flen; i += 384) fs[i] = fp[i];
    __syncthreads();

    int oc = t >> 2, q = t & 3;
    const float* fo = &fs[oc * fstr];
    float lsum = 0.f, lsq = 0.f;
    for (int p = q * 100; p < q * 100 + 100; p++) {
        int h = p / 20, w = p - h * 20;
        float acc = conv_point(xs, fo, brch, h, w);
        lsum += acc; lsq += acc * acc;
    }
    lsum += __shfl_down_sync(0xffffffffu, lsum, 2, 4);
    lsum += __shfl_down_sync(0xffffffffu, lsum, 1, 4);
    lsq  += __shfl_down_sync(0xffffffffu, lsq, 2, 4);
    lsq  += __shfl_down_sync(0xffffffffu, lsq, 1, 4);
    if (q == 0) {
        g_bsum[(brch * BSZ + b) * OC + oc] = lsum;
        atomicAdd(&g_chsum[brch * OC + oc], lsum);
        atomicAdd(&g_chsq[brch * OC + oc], lsq);
    }
}

// ---------------- kernel 3: BN affine ----------------
__global__ void bnaff(
    const float* __restrict__ g1, const float* __restrict__ b1,
    const float* __restrict__ g2, const float* __restrict__ b2,
    const float* __restrict__ g3, const float* __restrict__ b3)
{
    int i = threadIdx.x;
    if (i < 3 * OC) {
        int brch = i / OC, c = i - brch * OC;
        float N = (float)BSZ * HW;
        float mean = g_chsum[i] / N;
        float var  = g_chsq[i] / N - mean * mean;
        const float* g = brch == 0 ? g1 : (brch == 1 ? g2 : g3);
        const float* bb = brch == 0 ? b1 : (brch == 1 ? b2 : b3);
        float a = g[c] * rsqrtf(var + EPSB);
        g_alpha[i] = a;
        g_beta[i]  = bb[c] - mean * a;
    }
}

// ---------------- reductions ----------------
__device__ __forceinline__ float redsum128(float v, float* sm) {
    int t = threadIdx.x;
    sm[t] = v; __syncthreads();
    for (int s = 64; s > 0; s >>= 1) {
        if (t < s) sm[t] += sm[t + s];
        __syncthreads();
    }
    float r = sm[0]; __syncthreads();
    return r;
}
__device__ __forceinline__ float redmax128(float v, float* sm) {
    int t = threadIdx.x;
    sm[t] = v; __syncthreads();
    for (int s = 64; s > 0; s >>= 1) {
        if (t < s) sm[t] = fmaxf(sm[t], sm[t + s]);
        __syncthreads();
    }
    float r = sm[0]; __syncthreads();
    return r;
}

// ---------------- kernel 4: SE + ATT gates ----------------
__global__ void __launch_bounds__(128) gates(
    const float* __restrict__ s1w1, const float* __restrict__ s1w2,
    const float* __restrict__ s2w1, const float* __restrict__ s2w2,
    const float* __restrict__ s3w1, const float* __restrict__ s3w2,
    const float* __restrict__ aw1, const float* __restrict__ aw2)
{
    __shared__ float sm[128];
    int b = blockIdx.x, t = threadIdx.x;
    bool act = t < OC;
    int oc = act ? t : 0;

    const float* w1s[3] = {s1w1, s2w1, s3w1};
    const float* w2s[3] = {s1w2, s2w2, s3w2};

    float pool[3], seg[3];
    #pragma unroll
    for (int br = 0; br < 3; br++) {
        float p = fmaf(g_alpha[br * OC + oc],
                       g_bsum[(br * BSZ + b) * OC + oc] * (1.f / HW),
                       g_beta[br * OC + oc]);
        pool[br] = act ? p : 0.f;
    }
    #pragma unroll
    for (int br = 0; br < 3; br++) {
        float h0 = redsum128(act ? pool[br] * w1s[br][oc] : 0.f, sm);
        float h1 = redsum128(act ? pool[br] * w1s[br][OC + oc] : 0.f, sm);
        h0 = fmaxf(h0, 0.f); h1 = fmaxf(h1, 0.f);
        float lg = h0 * w2s[br][oc * 2] + h1 * w2s[br][oc * 2 + 1];
        seg[br] = 1.f / (1.f + expf(-lg));
    }
    float attp = seg[0] * pool[0] + seg[1] * pool[1] + seg[2] * pool[2];
    float a0 = fmaxf(redsum128(act ? attp * aw1[oc] : 0.f, sm), 0.f);
    float a1 = fmaxf(redsum128(act ? attp * aw1[OC + oc] : 0.f, sm), 0.f);

    float l[3], mx = -1e30f;
    #pragma unroll
    for (int br = 0; br < 3; br++) {
        l[br] = act ? (a0 * aw2[(br * OC + oc) * 2] + a1 * aw2[(br * OC + oc) * 2 + 1])
                    : -1e30f;
        mx = fmaxf(mx, l[br]);
    }
    float gm = redmax128(mx, sm);
    float e[3], le = 0.f;
    #pragma unroll
    for (int br = 0; br < 3; br++) { e[br] = expf(l[br] - gm); le += e[br]; }
    float S = redsum128(le, sm);
    if (act) {
        #pragma unroll
        for (int br = 0; br < 3; br++)
            g_scale[(br * BSZ + b) * OC + oc] = seg[br] * e[br] / S;
    }
}

// ---------------- kernel 2b: conv recompute + gate + relu -> fp16 ----------------
__global__ void __launch_bounds__(384) conv3_fused(
    const float* __restrict__ f1, const float* __restrict__ f2,
    const float* __restrict__ f3, const int* __restrict__ rel,
    const float* __restrict__ bn0g, const float* __restrict__ bn0b)
{
    __shared__ float xs[HW];
    __shared__ float fs[OC * 9];
    __shared__ float sA[OC], sBt[OC], sS[OC];
    int b = blockIdx.x, brch = blockIdx.y, t = threadIdx.x;

    float N0 = (float)BSZ * HW;
    float mean = g_bn0[0] / N0;
    float var  = g_bn0[1] / N0 - mean * mean;
    float a0 = bn0g[0] * rsqrtf(var + EPSB);
    float b0 = bn0b[0] - mean * a0;

    for (int i = t; i < HW; i += 384) xs[i] = g_x[b * HW + i] * a0 + b0;

    int rb = rel[b];
    int flen = (brch == 1) ? OC * 9 : OC * 5;
    int fstr = (brch == 1) ? 9 : 5;
    const float* fp = (brch == 0 ? f1 : (brch == 1 ? f2 : f3)) + (long)rb * flen;
    for (int i = t; i < flen; i += 384) fs[i] = fp[i];
    if (t < OC) {
        sA[t]  = g_alpha[brch * OC + t];
        sBt[t] = g_beta[brch * OC + t];
        sS[t]  = g_scale[(brch * BSZ + b) * OC + t];
    }
    __syncthreads();

    long obase = (long)b * NFC + (long)brch * (OC * HW);
    for (int i = t; i < OC * HW; i += 384) {
        int oc = i / HW, p = i - oc * HW;
        int h = p / 20, w = p - h * 20;
        float acc = conv_point(xs, &fs[oc * fstr], brch, h, w);
        float v = fmaxf(fmaf(sA[oc], acc, sBt[oc]) * sS[oc], 0.f);
        g_A[obase + i] = __float2half(v);
    }
}

// ---------------- split kernels ----------------
__global__ void __launch_bounds__(256) splitW(const float* __restrict__ w) {
    long i4 = (long)blockIdx.x * 256 + threadIdx.x;   // 22500 blocks x 4 floats
    float4 v = ((const float4*)w)[i4];
    __half h0 = __float2half(v.x), h1 = __float2half(v.y);
    __half h2 = __float2half(v.z), h3 = __float2half(v.w);
    __half2 hh0, hh1, ll0, ll1;
    hh0.x = h0; hh0.y = h1; hh1.x = h2; hh1.y = h3;
    ll0.x = __float2half(v.x - __half2float(h0));
    ll0.y = __float2half(v.y - __half2float(h1));
    ll1.x = __float2half(v.z - __half2float(h2));
    ll1.y = __float2half(v.w - __half2float(h3));
    ((__half2*)g_Wh)[i4 * 2]     = hh0;
    ((__half2*)g_Wh)[i4 * 2 + 1] = hh1;
    ((__half2*)g_Wl)[i4 * 2]     = ll0;
    ((__half2*)g_Wl)[i4 * 2 + 1] = ll1;
}

__global__ void __launch_bounds__(256) splitN(const float* __restrict__ nf) {
    long t = (long)blockIdx.x * 256 + threadIdx.x;   // 32500 blocks: 40000*208
    int e = (int)(t / KP2), j = (int)(t - (long)e * KP2);
    float v = (j < DW) ? nf[(long)e * DW + j] : 0.f;
    __half h = __float2half(v);
    g_nh[t] = h;
    g_nl[t] = __float2half(v - __half2float(h));
}

// ---------------- HMMA fp16x2 GEMM: 128x128 tile, kstep16, 3 stages, occ-2 ------
// smem stage = 3 planes (A, Bh, Bl) x [128 rows x 16 k] fp16 (4KB each) = 12KB
__device__ __forceinline__ void gemm_hmma(
    const __half* __restrict__ A, long lda,
    const __half* __restrict__ Bh, const __half* __restrict__ Bl, long ldb,
    float* __restrict__ C, long ldc, int Nn,
    int m0, int n0, long k0, int nk, const float* __restrict__ bias)
{
    __shared__ __align__(16) char smem[36864];
    unsigned sb = (unsigned)__cvta_generic_to_shared(smem);
    int tid = threadIdx.x, lane = tid & 31, wid = tid >> 5;
    int wm = (wid >> 2) * 64, wn = (wid & 3) * 32;

    float acc[4][4][4];
    #pragma unroll
    for (int i = 0; i < 4; i++)
        #pragma unroll
        for (int j = 0; j < 4; j++)
            #pragma unroll
            for (int k = 0; k < 4; k++) acc[i][j][k] = 0.f;

    // 768 chunks of 16B per stage; 3 per thread
    #define ISSUE(stg_, kb_) do {                                              \
        unsigned s0_ = sb + (unsigned)(stg_) * 12288u;                         \
        long kk_ = k0 + (long)(kb_) * 16;                                      \
        _Pragma("unroll")                                                      \
        for (int ii = 0; ii < 3; ii++) {                                       \
            int i_ = tid + ii * 256;                                           \
            int pl_ = i_ >> 8, r_ = (i_ >> 1) & 127, c_ = i_ & 1;              \
            unsigned sw_ = s0_ + (unsigned)pl_ * 4096u + (unsigned)r_ * 32u    \
                         + (unsigned)((c_ ^ ((r_ >> 2) & 1)) * 16);            \
            if (pl_ == 0) cpa16(sw_, A + (long)(m0 + r_) * lda + kk_ + c_ * 8);\
            else {                                                             \
                int ok_ = ((n0 + r_) < Nn) ? 16 : 0;                           \
                const __half* P_ = (pl_ == 1) ? Bh : Bl;                       \
                cpa16z(sw_, P_ + (long)(n0 + r_) * ldb + kk_ + c_ * 8, ok_);   \
            }                                                                  \
        }                                                                      \
        asm volatile("cp.async.commit_group;" ::: "memory");                   \
    } while (0)

    // per-warp ldmatrix offsets (stage-invariant)
    int cbit = lane >> 4;
    unsigned aoff[4], boff[2];
    #pragma unroll
    for (int mt = 0; mt < 4; mt++) {
        int r = wm + mt * 16 + (lane & 15);
        aoff[mt] = (unsigned)r * 32u + (unsigned)((cbit ^ ((r >> 2) & 1)) * 16);
    }
    #pragma unroll
    for (int j = 0; j < 2; j++) {
        int r = wn + j * 16 + (lane & 15);
        boff[j] = 4096u + (unsigned)r * 32u
                + (unsigned)((cbit ^ ((r >> 2) & 1)) * 16);
    }

    ISSUE(0, 0);
    ISSUE(1, 1);

    for (int kb = 0; kb < nk; kb++) {
        int st = kb % 3;
        if (kb + 1 < nk)
            asm volatile("cp.async.wait_group 1;" ::: "memory");
        else
            asm volatile("cp.async.wait_group 0;" ::: "memory");
        __syncthreads();
        if (kb + 2 < nk) ISSUE((kb + 2) % 3, kb + 2);   // prefetch early

        unsigned s0 = sb + (unsigned)st * 12288u;
        unsigned bh[2][4], bl[2][4];
        #pragma unroll
        for (int j = 0; j < 2; j++) {
            ldsm4(bh[j], s0 + boff[j]);
            ldsm4(bl[j], s0 + boff[j] + 4096u);
        }
        #pragma unroll
        for (int mt = 0; mt < 4; mt++) {
            unsigned ah[4];
            ldsm4(ah, s0 + aoff[mt]);
            #pragma unroll
            for (int j = 0; j < 2; j++) {
                mma_fp16(acc[mt][2*j],   ah, bh[j][0], bh[j][2]);
                mma_fp16(acc[mt][2*j],   ah, bl[j][0], bl[j][2]);
                mma_fp16(acc[mt][2*j+1], ah, bh[j][1], bh[j][3]);
                mma_fp16(acc[mt][2*j+1], ah, bl[j][1], bl[j][3]);
            }
        }
        __syncthreads();
    }
    #undef ISSUE

    #pragma unroll
    for (int mt = 0; mt < 4; mt++) {
        #pragma unroll
        for (int nt = 0; nt < 4; nt++) {
            int rr = m0 + wm + mt * 16 + (lane >> 2);
            int cc = n0 + wn + nt * 8 + (lane & 3) * 2;
            if (cc < Nn) {
                float bv0 = bias ? bias[cc] : 0.f;
                float bv1 = bias ? bias[cc + 1] : 0.f;
                C[(long)rr * ldc + cc]           = acc[mt][nt][0] + bv0;
                C[(long)rr * ldc + cc + 1]       = acc[mt][nt][1] + bv1;
                C[(long)(rr + 8) * ldc + cc]     = acc[mt][nt][2] + bv0;
                C[(long)(rr + 8) * ldc + cc + 1] = acc[mt][nt][3] + bv1;
            }
        }
    }
}

__global__ void __launch_bounds__(256, 2) gemm1_k() {
    gemm_hmma(g_A, NFC, g_Wh, g_Wl, NFC,
              g_c1p + (long)blockIdx.z * (BSZ * DW), DW, DW,
              blockIdx.y * 128, blockIdx.x * 128,
              (long)blockIdx.z * CH1, NK1, nullptr);
}

__global__ void __launch_bounds__(256, 2) gemm2_k(
    const float* __restrict__ biasb, float* __restrict__ out) {
    gemm_hmma(g_z, KP2, g_nh, g_nl, KP2,
              out, NENT, NENT,
              blockIdx.y * 128, blockIdx.x * 128, 0, NK2, biasb);
}

// ---------------- kernel 6: split-K reduce + fc bias ----------------
__global__ void __launch_bounds__(256) reduce_c1(const float* __restrict__ fcb) {
    int idx = blockIdx.x * 256 + threadIdx.x;     // 800*256 == 204800
    float s = 0.f;
    #pragma unroll
    for (int z = 0; z < SK1; z++) s += g_c1p[z * (BSZ * DW) + idx];
    g_c1[idx] = s + fcb[idx % DW];
}

// ---------------- kernel 7: BN1d + ReLU -> fp16 (padded to KP2) ----------------
__global__ void __launch_bounds__(256) bn2_relu(
    const float* __restrict__ g2, const float* __restrict__ b2) {
    int d = blockIdx.x, t = threadIdx.x;          // d in [0,KP2)
    if (d >= DW) {
        for (int b = t; b < BSZ; b += 256) g_z[b * KP2 + d] = __float2half(0.f);
        return;
    }
    float s = 0.f, q = 0.f;
    for (int b = t; b < BSZ; b += 256) {
        float v = g_c1[b * DW + d];
        s += v; q += v * v;
    }
    __shared__ float ss[256], sq[256];
    ss[t] = s; sq[t] = q; __syncthreads();
    for (int st = 128; st > 0; st >>= 1) {
        if (t < st) { ss[t] += ss[t + st]; sq[t] += sq[t + st]; }
        __syncthreads();
    }
    float mean = ss[0] / BSZ;
    float var  = sq[0] / BSZ - mean * mean;
    float a = g2[d] * rsqrtf(var + EPSB);
    float bb = b2[d] - mean * a;
    for (int b = t; b < BSZ; b += 256) {
        float v = fmaxf(fmaf(a, g_c1[b * DW + d], bb), 0.f);
        g_z[b * KP2 + d] = __float2half(v);
    }
}

// ---------------- launch ----------------
extern "C" void kernel_launch(void* const* d_in, const int* in_sizes, int n_in,
                              void* d_out, int out_size) {
    const float* n_feats = (const float*)d_in[0];
    const float* r_feats = (const float*)d_in[1];
    const float* filt1   = (const float*)d_in[2];
    const float* filt2   = (const float*)d_in[3];
    const float* filt3   = (const float*)d_in[4];
    const float* bn0_g   = (const float*)d_in[5];
    const float* bn0_b   = (const float*)d_in[6];
    const float* bn1_g   = (const float*)d_in[7];
    const float* bn1_b   = (const float*)d_in[8];
    const float* bn2c_g  = (const float*)d_in[9];
    const float* bn2c_b  = (const float*)d_in[10];
    const float* bn3c_g  = (const float*)d_in[11];
    const float* bn3c_b  = (const float*)d_in[12];
    const float* se1_w1  = (const float*)d_in[13];
    const float* se1_w2  = (const float*)d_in[14];
    const float* se2_w1  = (const float*)d_in[15];
    const float* se2_w2  = (const float*)d_in[16];
    const float* se3_w1  = (const float*)d_in[17];
    const float* se3_w2  = (const float*)d_in[18];
    const float* att_w1  = (const float*)d_in[19];
    const float* att_w2  = (const float*)d_in[20];
    const float* fc_w    = (const float*)d_in[21];
    const float* fc_b    = (const float*)d_in[22];
    const float* bn2_g   = (const float*)d_in[23];
    const float* bn2_b   = (const float*)d_in[24];
    const float* bias_b  = (const float*)d_in[25];
    const int*   sub     = (const int*)d_in[26];
    const int*   rel     = (const int*)d_in[27];

    zero_stats<<<1, 3 * OC>>>();
    splitW<<<22500, 256>>>(fc_w);
    splitN<<<32500, 256>>>(n_feats);
    gather_bn0<<<BSZ, 128>>>(n_feats, r_feats, sub, rel);
    conv3_stats<<<dim3(BSZ, 3), 384>>>(filt1, filt2, filt3, rel, bn0_g, bn0_b);
    bnaff<<<1, 3 * OC>>>(bn1_g, bn1_b, bn2c_g, bn2c_b, bn3c_g, bn3c_b);
    gates<<<BSZ, 128>>>(se1_w1, se1_w2, se2_w1, se2_w2, se3_w1, se3_w2,
                        att_w1, att_w2);
    conv3_fused<<<dim3(BSZ, 3), 384>>>(filt1, filt2, filt3, rel, bn0_g, bn0_b);
    gemm1_k<<<dim3(2, BSZ / 128, SK1), 256>>>();
    reduce_c1<<<800, 256>>>(fc_b);
    bn2_relu<<<KP2, 256>>>(bn2_g, bn2_b);
    gemm2_k<<<dim3((NENT + 127) / 128, BSZ / 128), 256>>>(bias_b, (float*)d_out);
}

// round 10
// speedup vs baseline: 1.5965x; 1.2013x over previous
#include <cuda_runtime.h>
#include <cuda_bf16.h>
#include <cuda_fp16.h>
#include <stdint.h>
#include <math.h>

// ---------------- problem constants ----------------
#define BSZ   1024
#define OC    96
#define DW    200          // d_embd
#define HW    400          // 20*20
#define NENT  40000
#define NFC   115200       // 3*96*400
#define EPSB  1e-5f
#define SK1   18
#define CH1   (NFC / SK1)  // 6400
#define NK1   (CH1 / 16)   // 400 k-steps of 16
#define KP2   208          // gemm2 K padded to mult of 16
#define NK2   (KP2 / 16)   // 13

// ---------------- device scratch ----------------
__device__ float g_x[BSZ * HW];
__device__ float g_bn0[2];
__device__ float g_bsum[3 * BSZ * OC];
__device__ float g_chsum[3 * OC];
__device__ float g_chsq[3 * OC];
__device__ float g_alpha[3 * OC];
__device__ float g_beta[3 * OC];
__device__ float g_scale[3 * BSZ * OC];
__device__ __align__(128) __half g_A [(long)BSZ * NFC];   // activations fp16
__device__ __align__(128) __half g_W [(long)DW * NFC];    // fc weight fp16
__device__ float g_c1p[SK1 * BSZ * DW];
__device__ float g_c1[BSZ * DW];
__device__ __align__(128) __half g_z [BSZ * KP2];         // BN2 output fp16
__device__ __align__(128) __half g_nh[(long)NENT * KP2];  // n_feats hi
__device__ __align__(128) __half g_nl[(long)NENT * KP2];  // n_feats lo

// ---------------- PTX helpers ----------------
__device__ __forceinline__ void ldsm4(unsigned r[4], unsigned addr) {
    asm volatile("ldmatrix.sync.aligned.m8n8.x4.shared.b16 {%0,%1,%2,%3}, [%4];"
        : "=r"(r[0]), "=r"(r[1]), "=r"(r[2]), "=r"(r[3]) : "r"(addr));
}
__device__ __forceinline__ void mma_fp16(float* c, const unsigned* a,
                                         unsigned b0, unsigned b1) {
    asm volatile(
        "mma.sync.aligned.m16n8k16.row.col.f32.f16.f16.f32 "
        "{%0,%1,%2,%3}, {%4,%5,%6,%7}, {%8,%9}, {%0,%1,%2,%3};"
        : "+f"(c[0]), "+f"(c[1]), "+f"(c[2]), "+f"(c[3])
        : "r"(a[0]), "r"(a[1]), "r"(a[2]), "r"(a[3]), "r"(b0), "r"(b1));
}
__device__ __forceinline__ void cpa16(unsigned s, const void* g) {
    asm volatile("cp.async.ca.shared.global [%0], [%1], 16;" :: "r"(s), "l"(g));
}
__device__ __forceinline__ void cpa16z(unsigned s, const void* g, int srcsz) {
    asm volatile("cp.async.ca.shared.global [%0], [%1], 16, %2;"
                 :: "r"(s), "l"(g), "r"(srcsz));
}

// ---------------- kernel 0: zero atomics ----------------
__global__ void zero_stats() {
    int t = threadIdx.x;
    if (t < 2) g_bn0[t] = 0.f;
    if (t < 3 * OC) { g_chsum[t] = 0.f; g_chsq[t] = 0.f; }
}

// ---------------- kernel 1: gather + chequer + BN0 stats ----------------
__global__ void __launch_bounds__(128) gather_bn0(
    const float* __restrict__ n_feats, const float* __restrict__ r_feats,
    const int* __restrict__ sub, const int* __restrict__ rel)
{
    int b = blockIdx.x, t = threadIdx.x;
    int sb = sub[b], rb = rel[b];
    float s = 0.f, q = 0.f;
    for (int i = t; i < HW; i += 128) {
        float v = (i & 1) ? r_feats[rb * DW + (i >> 1)]
                          : n_feats[sb * DW + (i >> 1)];
        g_x[b * HW + i] = v;
        s += v; q += v * v;
    }
    __shared__ float ss[128], sq[128];
    ss[t] = s; sq[t] = q; __syncthreads();
    for (int st = 64; st > 0; st >>= 1) {
        if (t < st) { ss[t] += ss[t + st]; sq[t] += sq[t + st]; }
        __syncthreads();
    }
    if (t == 0) { atomicAdd(&g_bn0[0], ss[0]); atomicAdd(&g_bn0[1], sq[0]); }
}

// ---------------- conv helpers ----------------
__device__ __forceinline__ float conv_point(
    const float* __restrict__ xs, const float* __restrict__ fo,
    int brch, int h, int w)
{
    float acc = 0.f;
    if (brch == 0) {
        const float* xr = &xs[h * 20];
        acc = xr[w] * fo[2];
        if (w >= 2)  acc += xr[w - 2] * fo[0];
        if (w >= 1)  acc += xr[w - 1] * fo[1];
        if (w <= 18) acc += xr[w + 1] * fo[3];
        if (w <= 17) acc += xr[w + 2] * fo[4];
    } else if (brch == 1) {
        #pragma unroll
        for (int dh = 0; dh < 3; dh++) {
            int hh = h + dh - 1;
            if (hh < 0 || hh >= 20) continue;
            const float* xr = &xs[hh * 20];
            #pragma unroll
            for (int dw = 0; dw < 3; dw++) {
                int ww = w + dw - 1;
                if (ww >= 0 && ww < 20) acc += xr[ww] * fo[dh * 3 + dw];
            }
        }
    } else {
        #pragma unroll
        for (int dh = 0; dh < 5; dh++) {
            int hh = h + dh - 2;
            if (hh >= 0 && hh < 20) acc += xs[hh * 20 + w] * fo[dh];
        }
    }
    return acc;
}

// ---------------- kernel 2a: conv stats pass ----------------
__global__ void __launch_bounds__(384) conv3_stats(
    const float* __restrict__ f1, const float* __restrict__ f2,
    const float* __restrict__ f3, const int* __restrict__ rel,
    const float* __restrict__ bn0g, const float* __restrict__ bn0b)
{
    __shared__ float xs[HW];
    __shared__ float fs[OC * 9];
    int b = blockIdx.x, brch = blockIdx.y, t = threadIdx.x;

    float N0 = (float)BSZ * HW;
    float mean = g_bn0[0] / N0;
    float var  = g_bn0[1] / N0 - mean * mean;
    float a0 = bn0g[0] * rsqrtf(var + EPSB);
    float b0 = bn0b[0] - mean * a0;

    for (int i = t; i < HW; i += 384) xs[i] = g_x[b * HW + i] * a0 + b0;

    int rb = rel[b];
    int flen = (brch == 1) ? OC * 9 : OC * 5;
    int fstr = (brch == 1) ? 9 : 5;
    const float* fp = (brch == 0 ? f1 : (brch == 1 ? f2 : f3)) + (long)rb * flen;
    for (int i = t; i < flen; i += 384) fs[i] = fp[i];
    __syncthreads();

    int oc = t >> 2, q = t & 3;
    const float* fo = &fs[oc * fstr];
    float lsum = 0.f, lsq = 0.f;
    for (int p = q * 100; p < q * 100 + 100; p++) {
        int h = p / 20, w = p - h * 20;
        float acc = conv_point(xs, fo, brch, h, w);
        lsum += acc; lsq += acc * acc;
    }
    lsum += __shfl_down_sync(0xffffffffu, lsum, 2, 4);
    lsum += __shfl_down_sync(0xffffffffu, lsum, 1, 4);
    lsq  += __shfl_down_sync(0xffffffffu, lsq, 2, 4);
    lsq  += __shfl_down_sync(0xffffffffu, lsq, 1, 4);
    if (q == 0) {
        g_bsum[(brch * BSZ + b) * OC + oc] = lsum;
        atomicAdd(&g_chsum[brch * OC + oc], lsum);
        atomicAdd(&g_chsq[brch * OC + oc], lsq);
    }
}

// ---------------- kernel 3: BN affine ----------------
__global__ void bnaff(
    const float* __restrict__ g1, const float* __restrict__ b1,
    const float* __restrict__ g2, const float* __restrict__ b2,
    const float* __restrict__ g3, const float* __restrict__ b3)
{
    int i = threadIdx.x;
    if (i < 3 * OC) {
        int brch = i / OC, c = i - brch * OC;
        float N = (float)BSZ * HW;
        float mean = g_chsum[i] / N;
        float var  = g_chsq[i] / N - mean * mean;
        const float* g = brch == 0 ? g1 : (brch == 1 ? g2 : g3);
        const float* bb = brch == 0 ? b1 : (brch == 1 ? b2 : b3);
        float a = g[c] * rsqrtf(var + EPSB);
        g_alpha[i] = a;
        g_beta[i]  = bb[c] - mean * a;
    }
}

// ---------------- reductions ----------------
__device__ __forceinline__ float redsum128(float v, float* sm) {
    int t = threadIdx.x;
    sm[t] = v; __syncthreads();
    for (int s = 64; s > 0; s >>= 1) {
        if (t < s) sm[t] += sm[t + s];
        __syncthreads();
    }
    float r = sm[0]; __syncthreads();
    return r;
}
__device__ __forceinline__ float redmax128(float v, float* sm) {
    int t = threadIdx.x;
    sm[t] = v; __syncthreads();
    for (int s = 64; s > 0; s >>= 1) {
        if (t < s) sm[t] = fmaxf(sm[t], sm[t + s]);
        __syncthreads();
    }
    float r = sm[0]; __syncthreads();
    return r;
}

// ---------------- kernel 4: SE + ATT gates ----------------
__global__ void __launch_bounds__(128) gates(
    const float* __restrict__ s1w1, const float* __restrict__ s1w2,
    const float* __restrict__ s2w1, const float* __restrict__ s2w2,
    const float* __restrict__ s3w1, const float* __restrict__ s3w2,
    const float* __restrict__ aw1, const float* __restrict__ aw2)
{
    __shared__ float sm[128];
    int b = blockIdx.x, t = threadIdx.x;
    bool act = t < OC;
    int oc = act ? t : 0;

    const float* w1s[3] = {s1w1, s2w1, s3w1};
    const float* w2s[3] = {s1w2, s2w2, s3w2};

    float pool[3], seg[3];
    #pragma unroll
    for (int br = 0; br < 3; br++) {
        float p = fmaf(g_alpha[br * OC + oc],
                       g_bsum[(br * BSZ + b) * OC + oc] * (1.f / HW),
                       g_beta[br * OC + oc]);
        pool[br] = act ? p : 0.f;
    }
    #pragma unroll
    for (int br = 0; br < 3; br++) {
        float h0 = redsum128(act ? pool[br] * w1s[br][oc] : 0.f, sm);
        float h1 = redsum128(act ? pool[br] * w1s[br][OC + oc] : 0.f, sm);
        h0 = fmaxf(h0, 0.f); h1 = fmaxf(h1, 0.f);
        float lg = h0 * w2s[br][oc * 2] + h1 * w2s[br][oc * 2 + 1];
        seg[br] = 1.f / (1.f + expf(-lg));
    }
    float attp = seg[0] * pool[0] + seg[1] * pool[1] + seg[2] * pool[2];
    float a0 = fmaxf(redsum128(act ? attp * aw1[oc] : 0.f, sm), 0.f);
    float a1 = fmaxf(redsum128(act ? attp * aw1[OC + oc] : 0.f, sm), 0.f);

    float l[3], mx = -1e30f;
    #pragma unroll
    for (int br = 0; br < 3; br++) {
        l[br] = act ? (a0 * aw2[(br * OC + oc) * 2] + a1 * aw2[(br * OC + oc) * 2 + 1])
                    : -1e30f;
        mx = fmaxf(mx, l[br]);
    }
    float gm = redmax128(mx, sm);
    float e[3], le = 0.f;
    #pragma unroll
    for (int br = 0; br < 3; br++) { e[br] = expf(l[br] - gm); le += e[br]; }
    float S = redsum128(le, sm);
    if (act) {
        #pragma unroll
        for (int br = 0; br < 3; br++)
            g_scale[(br * BSZ + b) * OC + oc] = seg[br] * e[br] / S;
    }
}

// ---------------- kernel 2b: conv recompute + gate + relu -> fp16 ----------------
__global__ void __launch_bounds__(384) conv3_fused(
    const float* __restrict__ f1, const float* __restrict__ f2,
    const float* __restrict__ f3, const int* __restrict__ rel,
    const float* __restrict__ bn0g, const float* __restrict__ bn0b)
{
    __shared__ float xs[HW];
    __shared__ float fs[OC * 9];
    __shared__ float sA[OC], sBt[OC], sS[OC];
    int b = blockIdx.x, brch = blockIdx.y, t = threadIdx.x;

    float N0 = (float)BSZ * HW;
    float mean = g_bn0[0] / N0;
    float var  = g_bn0[1] / N0 - mean * mean;
    float a0 = bn0g[0] * rsqrtf(var + EPSB);
    float b0 = bn0b[0] - mean * a0;

    for (int i = t; i < HW; i += 384) xs[i] = g_x[b * HW + i] * a0 + b0;

    int rb = rel[b];
    int flen = (brch == 1) ? OC * 9 : OC * 5;
    int fstr = (brch == 1) ? 9 : 5;
    const float* fp = (brch == 0 ? f1 : (brch == 1 ? f2 : f3)) + (long)rb * flen;
    for (int i = t; i < flen; i += 384) fs[i] = fp[i];
    if (t < OC) {
        sA[t]  = g_alpha[brch * OC + t];
        sBt[t] = g_beta[brch * OC + t];
        sS[t]  = g_scale[(brch * BSZ + b) * OC + t];
    }
    __syncthreads();

    long obase = (long)b * NFC + (long)brch * (OC * HW);
    for (int i = t; i < OC * HW; i += 384) {
        int oc = i / HW, p = i - oc * HW;
        int h = p / 20, w = p - h * 20;
        float acc = conv_point(xs, &fs[oc * fstr], brch, h, w);
        float v = fmaxf(fmaf(sA[oc], acc, sBt[oc]) * sS[oc], 0.f);
        g_A[obase + i] = __float2half(v);
    }
}

// ---------------- split/convert kernels ----------------
__global__ void __launch_bounds__(256) convW(const float* __restrict__ w) {
    long i4 = (long)blockIdx.x * 256 + threadIdx.x;   // 22500 blocks x 4 floats
    float4 v = ((const float4*)w)[i4];
    __half2 hh0, hh1;
    hh0.x = __float2half(v.x); hh0.y = __float2half(v.y);
    hh1.x = __float2half(v.z); hh1.y = __float2half(v.w);
    ((__half2*)g_W)[i4 * 2]     = hh0;
    ((__half2*)g_W)[i4 * 2 + 1] = hh1;
}

__global__ void __launch_bounds__(256) splitN(const float* __restrict__ nf) {
    long t = (long)blockIdx.x * 256 + threadIdx.x;   // 32500 blocks: 40000*208
    int e = (int)(t / KP2), j = (int)(t - (long)e * KP2);
    float v = (j < DW) ? nf[(long)e * DW + j] : 0.f;
    __half h = __float2half(v);
    g_nh[t] = h;
    g_nl[t] = __float2half(v - __half2float(h));
}

// ---------------- HMMA fp16 GEMM: 128x128 tile, kstep16, 3 stages, occ-2 --------
// NPL = number of B planes (1 or 2). smem stage = (1+NPL) x 4KB.
template<int NPL>
__device__ __forceinline__ void gemm_hmma(
    const __half* __restrict__ A, long lda,
    const __half* __restrict__ Bh, const __half* __restrict__ Bl, long ldb,
    float* __restrict__ C, long ldc, int Nn,
    int m0, int n0, long k0, int nk, const float* __restrict__ bias)
{
    constexpr int PLANES = 1 + NPL;
    constexpr unsigned STG = (unsigned)PLANES * 4096u;
    __shared__ __align__(16) char smem[3 * PLANES * 4096];
    unsigned sb = (unsigned)__cvta_generic_to_shared(smem);
    int tid = threadIdx.x, lane = tid & 31, wid = tid >> 5;
    int wm = (wid >> 2) * 64, wn = (wid & 3) * 32;

    float acc[4][4][4];
    #pragma unroll
    for (int i = 0; i < 4; i++)
        #pragma unroll
        for (int j = 0; j < 4; j++)
            #pragma unroll
            for (int k = 0; k < 4; k++) acc[i][j][k] = 0.f;

    auto issue = [&](int stg_, int kb_) {
        unsigned s0_ = sb + (unsigned)stg_ * STG;
        long kk_ = k0 + (long)kb_ * 16;
        #pragma unroll
        for (int ii = 0; ii < PLANES; ii++) {
            int i_ = tid + ii * 256;
            int pl_ = i_ >> 8, r_ = (i_ >> 1) & 127, c_ = i_ & 1;
            unsigned sw_ = s0_ + (unsigned)pl_ * 4096u + (unsigned)r_ * 32u
                         + (unsigned)((c_ ^ ((r_ >> 2) & 1)) * 16);
            if (pl_ == 0) {
                cpa16(sw_, A + (long)(m0 + r_) * lda + kk_ + c_ * 8);
            } else {
                int ok_ = ((n0 + r_) < Nn) ? 16 : 0;
                const __half* P_ = (pl_ == 1) ? Bh : Bl;
                cpa16z(sw_, P_ + (long)(n0 + r_) * ldb + kk_ + c_ * 8, ok_);
            }
        }
        asm volatile("cp.async.commit_group;" ::: "memory");
    };

    // per-warp ldmatrix offsets (stage-invariant)
    int cbit = lane >> 4;
    unsigned aoff[4], boff[2];
    #pragma unroll
    for (int mt = 0; mt < 4; mt++) {
        int r = wm + mt * 16 + (lane & 15);
        aoff[mt] = (unsigned)r * 32u + (unsigned)((cbit ^ ((r >> 2) & 1)) * 16);
    }
    #pragma unroll
    for (int j = 0; j < 2; j++) {
        int r = wn + j * 16 + (lane & 15);
        boff[j] = 4096u + (unsigned)r * 32u
                + (unsigned)((cbit ^ ((r >> 2) & 1)) * 16);
    }

    issue(0, 0);
    issue(1, 1);

    for (int kb = 0; kb < nk; kb++) {
        int st = kb % 3;
        if (kb + 1 < nk)
            asm volatile("cp.async.wait_group 1;" ::: "memory");
        else
            asm volatile("cp.async.wait_group 0;" ::: "memory");
        __syncthreads();
        if (kb + 2 < nk) issue((kb + 2) % 3, kb + 2);   // prefetch early

        unsigned s0 = sb + (unsigned)st * STG;
        unsigned bh[2][4], bl[2][4];
        #pragma unroll
        for (int j = 0; j < 2; j++) {
            ldsm4(bh[j], s0 + boff[j]);
            if (NPL == 2) ldsm4(bl[j], s0 + boff[j] + 4096u);
        }
        #pragma unroll
        for (int mt = 0; mt < 4; mt++) {
            unsigned ah[4];
            ldsm4(ah, s0 + aoff[mt]);
            #pragma unroll
            for (int j = 0; j < 2; j++) {
                mma_fp16(acc[mt][2*j],   ah, bh[j][0], bh[j][2]);
                mma_fp16(acc[mt][2*j+1], ah, bh[j][1], bh[j][3]);
                if (NPL == 2) {
                    mma_fp16(acc[mt][2*j],   ah, bl[j][0], bl[j][2]);
                    mma_fp16(acc[mt][2*j+1], ah, bl[j][1], bl[j][3]);
                }
            }
        }
        __syncthreads();
    }

    #pragma unroll
    for (int mt = 0; mt < 4; mt++) {
        #pragma unroll
        for (int nt = 0; nt < 4; nt++) {
            int rr = m0 + wm + mt * 16 + (lane >> 2);
            int cc = n0 + wn + nt * 8 + (lane & 3) * 2;
            if (cc < Nn) {
                float bv0 = bias ? bias[cc] : 0.f;
                float bv1 = bias ? bias[cc + 1] : 0.f;
                C[(long)rr * ldc + cc]           = acc[mt][nt][0] + bv0;
                C[(long)rr * ldc + cc + 1]       = acc[mt][nt][1] + bv1;
                C[(long)(rr + 8) * ldc + cc]     = acc[mt][nt][2] + bv0;
                C[(long)(rr + 8) * ldc + cc + 1] = acc[mt][nt][3] + bv1;
            }
        }
    }
}

__global__ void __launch_bounds__(256, 2) gemm1_k() {
    gemm_hmma<1>(g_A, NFC, g_W, nullptr, NFC,
                 g_c1p + (long)blockIdx.z * (BSZ * DW), DW, DW,
                 blockIdx.y * 128, blockIdx.x * 128,
                 (long)blockIdx.z * CH1, NK1, nullptr);
}

__global__ void __launch_bounds__(256, 2) gemm2_k(
    const float* __restrict__ biasb, float* __restrict__ out) {
    gemm_hmma<2>(g_z, KP2, g_nh, g_nl, KP2,
                 out, NENT, NENT,
                 blockIdx.y * 128, blockIdx.x * 128, 0, NK2, biasb);
}

// ---------------- kernel 6: split-K reduce + fc bias ----------------
__global__ void __launch_bounds__(256) reduce_c1(const float* __restrict__ fcb) {
    int idx = blockIdx.x * 256 + threadIdx.x;     // 800*256 == 204800
    float s = 0.f;
    #pragma unroll
    for (int z = 0; z < SK1; z++) s += g_c1p[z * (BSZ * DW) + idx];
    g_c1[idx] = s + fcb[idx % DW];
}

// ---------------- kernel 7: BN1d + ReLU -> fp16 (padded to KP2) ----------------
__global__ void __launch_bounds__(256) bn2_relu(
    const float* __restrict__ g2, const float* __restrict__ b2) {
    int d = blockIdx.x, t = threadIdx.x;          // d in [0,KP2)
    if (d >= DW) {
        for (int b = t; b < BSZ; b += 256) g_z[b * KP2 + d] = __float2half(0.f);
        return;
    }
    float s = 0.f, q = 0.f;
    for (int b = t; b < BSZ; b += 256) {
        float v = g_c1[b * DW + d];
        s += v; q += v * v;
    }
    __shared__ float ss[256], sq[256];
    ss[t] = s; sq[t] = q; __syncthreads();
    for (int st = 128; st > 0; st >>= 1) {
        if (t < st) { ss[t] += ss[t + st]; sq[t] += sq[t + st]; }
        __syncthreads();
    }
    float mean = ss[0] / BSZ;
    float var  = sq[0] / BSZ - mean * mean;
    float a = g2[d] * rsqrtf(var + EPSB);
    float bb = b2[d] - mean * a;
    for (int b = t; b < BSZ; b += 256) {
        float v = fmaxf(fmaf(a, g_c1[b * DW + d], bb), 0.f);
        g_z[b * KP2 + d] = __float2half(v);
    }
}

// ---------------- launch ----------------
extern "C" void kernel_launch(void* const* d_in, const int* in_sizes, int n_in,
                              void* d_out, int out_size) {
    const float* n_feats = (const float*)d_in[0];
    const float* r_feats = (const float*)d_in[1];
    const float* filt1   = (const float*)d_in[2];
    const float* filt2   = (const float*)d_in[3];
    const float* filt3   = (const float*)d_in[4];
    const float* bn0_g   = (const float*)d_in[5];
    const float* bn0_b   = (const float*)d_in[6];
    const float* bn1_g   = (const float*)d_in[7];
    const float* bn1_b   = (const float*)d_in[8];
    const float* bn2c_g  = (const float*)d_in[9];
    const float* bn2c_b  = (const float*)d_in[10];
    const float* bn3c_g  = (const float*)d_in[11];
    const float* bn3c_b  = (const float*)d_in[12];
    const float* se1_w1  = (const float*)d_in[13];
    const float* se1_w2  = (const float*)d_in[14];
    const float* se2_w1  = (const float*)d_in[15];
    const float* se2_w2  = (const float*)d_in[16];
    const float* se3_w1  = (const float*)d_in[17];
    const float* se3_w2  = (const float*)d_in[18];
    const float* att_w1  = (const float*)d_in[19];
    const float* att_w2  = (const float*)d_in[20];
    const float* fc_w    = (const float*)d_in[21];
    const float* fc_b    = (const float*)d_in[22];
    const float* bn2_g   = (const float*)d_in[23];
    const float* bn2_b   = (const float*)d_in[24];
    const float* bias_b  = (const float*)d_in[25];
    const int*   sub     = (const int*)d_in[26];
    const int*   rel     = (const int*)d_in[27];

    zero_stats<<<1, 3 * OC>>>();
    convW<<<22500, 256>>>(fc_w);
    splitN<<<32500, 256>>>(n_feats);
    gather_bn0<<<BSZ, 128>>>(n_feats, r_feats, sub, rel);
    conv3_stats<<<dim3(BSZ, 3), 384>>>(filt1, filt2, filt3, rel, bn0_g, bn0_b);
    bnaff<<<1, 3 * OC>>>(bn1_g, bn1_b, bn2c_g, bn2c_b, bn3c_g, bn3c_b);
    gates<<<BSZ, 128>>>(se1_w1, se1_w2, se2_w1, se2_w2, se3_w1, se3_w2,
                        att_w1, att_w2);
    conv3_fused<<<dim3(BSZ, 3), 384>>>(filt1, filt2, filt3, rel, bn0_g, bn0_b);
    gemm1_k<<<dim3(2, BSZ / 128, SK1), 256>>>();
    reduce_c1<<<800, 256>>>(fc_b);
    bn2_relu<<<KP2, 256>>>(bn2_g, bn2_b);
    gemm2_k<<<dim3((NENT + 127) / 128, BSZ / 128), 256>>>(bias_b, (float*)d_out);
}

// round 11
// speedup vs baseline: 1.6709x; 1.0466x over previous
#include <cuda_runtime.h>
#include <cuda_bf16.h>
#include <cuda_fp16.h>
#include <stdint.h>
#include <math.h>

// ---------------- problem constants ----------------
#define BSZ   1024
#define OC    96
#define DW    200          // d_embd
#define HW    400          // 20*20
#define NENT  40000
#define NFC   115200       // 3*96*400
#define EPSB  1e-5f
#define SK1   18
#define CH1   (NFC / SK1)  // 6400
#define NK1   (CH1 / 16)   // 400 k-steps of 16
#define KP2   208          // gemm2 K padded to mult of 16
#define NK2   (KP2 / 16)   // 13

// ---------------- device scratch ----------------
__device__ float g_x[BSZ * HW];
__device__ float g_bn0[2];
__device__ float g_bsum[3 * BSZ * OC];
__device__ float g_chsum[3 * OC];
__device__ float g_chsq[3 * OC];
__device__ float g_alpha[3 * OC];
__device__ float g_beta[3 * OC];
__device__ float g_scale[3 * BSZ * OC];
__device__ __align__(128) __half g_A [(long)BSZ * NFC];   // activations fp16
__device__ __align__(128) __half g_W [(long)DW * NFC];    // fc weight fp16
__device__ float g_c1p[SK1 * BSZ * DW];
__device__ float g_c1[BSZ * DW];
__device__ __align__(128) __half g_z [BSZ * KP2];         // BN2 output fp16
__device__ __align__(128) __half g_n [(long)NENT * KP2];  // n_feats fp16

// ---------------- PTX helpers ----------------
__device__ __forceinline__ void ldsm4(unsigned r[4], unsigned addr) {
    asm volatile("ldmatrix.sync.aligned.m8n8.x4.shared.b16 {%0,%1,%2,%3}, [%4];"
        : "=r"(r[0]), "=r"(r[1]), "=r"(r[2]), "=r"(r[3]) : "r"(addr));
}
__device__ __forceinline__ void mma_fp16(float* c, const unsigned* a,
                                         unsigned b0, unsigned b1) {
    asm volatile(
        "mma.sync.aligned.m16n8k16.row.col.f32.f16.f16.f32 "
        "{%0,%1,%2,%3}, {%4,%5,%6,%7}, {%8,%9}, {%0,%1,%2,%3};"
        : "+f"(c[0]), "+f"(c[1]), "+f"(c[2]), "+f"(c[3])
        : "r"(a[0]), "r"(a[1]), "r"(a[2]), "r"(a[3]), "r"(b0), "r"(b1));
}
__device__ __forceinline__ void cpa16(unsigned s, const void* g) {
    asm volatile("cp.async.ca.shared.global [%0], [%1], 16;" :: "r"(s), "l"(g));
}
__device__ __forceinline__ void cpa16z(unsigned s, const void* g, int srcsz) {
    asm volatile("cp.async.ca.shared.global [%0], [%1], 16, %2;"
                 :: "r"(s), "l"(g), "r"(srcsz));
}

// ---------------- kernel 0: zero atomics ----------------
__global__ void zero_stats() {
    int t = threadIdx.x;
    if (t < 2) g_bn0[t] = 0.f;
    if (t < 3 * OC) { g_chsum[t] = 0.f; g_chsq[t] = 0.f; }
}

// ---------------- kernel 1: gather + chequer + BN0 stats ----------------
__global__ void __launch_bounds__(128) gather_bn0(
    const float* __restrict__ n_feats, const float* __restrict__ r_feats,
    const int* __restrict__ sub, const int* __restrict__ rel)
{
    int b = blockIdx.x, t = threadIdx.x;
    int sb = sub[b], rb = rel[b];
    float s = 0.f, q = 0.f;
    for (int i = t; i < HW; i += 128) {
        float v = (i & 1) ? r_feats[rb * DW + (i >> 1)]
                          : n_feats[sb * DW + (i >> 1)];
        g_x[b * HW + i] = v;
        s += v; q += v * v;
    }
    __shared__ float ss[128], sq[128];
    ss[t] = s; sq[t] = q; __syncthreads();
    for (int st = 64; st > 0; st >>= 1) {
        if (t < st) { ss[t] += ss[t + st]; sq[t] += sq[t + st]; }
        __syncthreads();
    }
    if (t == 0) { atomicAdd(&g_bn0[0], ss[0]); atomicAdd(&g_bn0[1], sq[0]); }
}

// ---------------- conv helpers ----------------
__device__ __forceinline__ float conv_point(
    const float* __restrict__ xs, const float* __restrict__ fo,
    int brch, int h, int w)
{
    float acc = 0.f;
    if (brch == 0) {
        const float* xr = &xs[h * 20];
        acc = xr[w] * fo[2];
        if (w >= 2)  acc += xr[w - 2] * fo[0];
        if (w >= 1)  acc += xr[w - 1] * fo[1];
        if (w <= 18) acc += xr[w + 1] * fo[3];
        if (w <= 17) acc += xr[w + 2] * fo[4];
    } else if (brch == 1) {
        #pragma unroll
        for (int dh = 0; dh < 3; dh++) {
            int hh = h + dh - 1;
            if (hh < 0 || hh >= 20) continue;
            const float* xr = &xs[hh * 20];
            #pragma unroll
            for (int dw = 0; dw < 3; dw++) {
                int ww = w + dw - 1;
                if (ww >= 0 && ww < 20) acc += xr[ww] * fo[dh * 3 + dw];
            }
        }
    } else {
        #pragma unroll
        for (int dh = 0; dh < 5; dh++) {
            int hh = h + dh - 2;
            if (hh >= 0 && hh < 20) acc += xs[hh * 20 + w] * fo[dh];
        }
    }
    return acc;
}

// ---------------- kernel 2a: conv stats pass ----------------
__global__ void __launch_bounds__(384) conv3_stats(
    const float* __restrict__ f1, const float* __restrict__ f2,
    const float* __restrict__ f3, const int* __restrict__ rel,
    const float* __restrict__ bn0g, const float* __restrict__ bn0b)
{
    __shared__ float xs[HW];
    __shared__ float fs[OC * 9];
    int b = blockIdx.x, brch = blockIdx.y, t = threadIdx.x;

    float N0 = (float)BSZ * HW;
    float mean = g_bn0[0] / N0;
    float var  = g_bn0[1] / N0 - mean * mean;
    float a0 = bn0g[0] * rsqrtf(var + EPSB);
    float b0 = bn0b[0] - mean * a0;

    for (int i = t; i < HW; i += 384) xs[i] = g_x[b * HW + i] * a0 + b0;

    int rb = rel[b];
    int flen = (brch == 1) ? OC * 9 : OC * 5;
    int fstr = (brch == 1) ? 9 : 5;
    const float* fp = (brch == 0 ? f1 : (brch == 1 ? f2 : f3)) + (long)rb * flen;
    for (int i = t; i < flen; i += 384) fs[i] = fp[i];
    __syncthreads();

    int oc = t >> 2, q = t & 3;
    const float* fo = &fs[oc * fstr];
    float lsum = 0.f, lsq = 0.f;
    for (int p = q * 100; p < q * 100 + 100; p++) {
        int h = p / 20, w = p - h * 20;
        float acc = conv_point(xs, fo, brch, h, w);
        lsum += acc; lsq += acc * acc;
    }
    lsum += __shfl_down_sync(0xffffffffu, lsum, 2, 4);
    lsum += __shfl_down_sync(0xffffffffu, lsum, 1, 4);
    lsq  += __shfl_down_sync(0xffffffffu, lsq, 2, 4);
    lsq  += __shfl_down_sync(0xffffffffu, lsq, 1, 4);
    if (q == 0) {
        g_bsum[(brch * BSZ + b) * OC + oc] = lsum;
        atomicAdd(&g_chsum[brch * OC + oc], lsum);
        atomicAdd(&g_chsq[brch * OC + oc], lsq);
    }
}

// ---------------- kernel 3: BN affine ----------------
__global__ void bnaff(
    const float* __restrict__ g1, const float* __restrict__ b1,
    const float* __restrict__ g2, const float* __restrict__ b2,
    const float* __restrict__ g3, const float* __restrict__ b3)
{
    int i = threadIdx.x;
    if (i < 3 * OC) {
        int brch = i / OC, c = i - brch * OC;
        float N = (float)BSZ * HW;
        float mean = g_chsum[i] / N;
        float var  = g_chsq[i] / N - mean * mean;
        const float* g = brch == 0 ? g1 : (brch == 1 ? g2 : g3);
        const float* bb = brch == 0 ? b1 : (brch == 1 ? b2 : b3);
        float a = g[c] * rsqrtf(var + EPSB);
        g_alpha[i] = a;
        g_beta[i]  = bb[c] - mean * a;
    }
}

// ---------------- reductions ----------------
__device__ __forceinline__ float redsum128(float v, float* sm) {
    int t = threadIdx.x;
    sm[t] = v; __syncthreads();
    for (int s = 64; s > 0; s >>= 1) {
        if (t < s) sm[t] += sm[t + s];
        __syncthreads();
    }
    float r = sm[0]; __syncthreads();
    return r;
}
__device__ __forceinline__ float redmax128(float v, float* sm) {
    int t = threadIdx.x;
    sm[t] = v; __syncthreads();
    for (int s = 64; s > 0; s >>= 1) {
        if (t < s) sm[t] = fmaxf(sm[t], sm[t + s]);
        __syncthreads();
    }
    float r = sm[0]; __syncthreads();
    return r;
}

// ---------------- kernel 4: SE + ATT gates ----------------
__global__ void __launch_bounds__(128) gates(
    const float* __restrict__ s1w1, const float* __restrict__ s1w2,
    const float* __restrict__ s2w1, const float* __restrict__ s2w2,
    const float* __restrict__ s3w1, const float* __restrict__ s3w2,
    const float* __restrict__ aw1, const float* __restrict__ aw2)
{
    __shared__ float sm[128];
    int b = blockIdx.x, t = threadIdx.x;
    bool act = t < OC;
    int oc = act ? t : 0;

    const float* w1s[3] = {s1w1, s2w1, s3w1};
    const float* w2s[3] = {s1w2, s2w2, s3w2};

    float pool[3], seg[3];
    #pragma unroll
    for (int br = 0; br < 3; br++) {
        float p = fmaf(g_alpha[br * OC + oc],
                       g_bsum[(br * BSZ + b) * OC + oc] * (1.f / HW),
                       g_beta[br * OC + oc]);
        pool[br] = act ? p : 0.f;
    }
    #pragma unroll
    for (int br = 0; br < 3; br++) {
        float h0 = redsum128(act ? pool[br] * w1s[br][oc] : 0.f, sm);
        float h1 = redsum128(act ? pool[br] * w1s[br][OC + oc] : 0.f, sm);
        h0 = fmaxf(h0, 0.f); h1 = fmaxf(h1, 0.f);
        float lg = h0 * w2s[br][oc * 2] + h1 * w2s[br][oc * 2 + 1];
        seg[br] = 1.f / (1.f + expf(-lg));
    }
    float attp = seg[0] * pool[0] + seg[1] * pool[1] + seg[2] * pool[2];
    float a0 = fmaxf(redsum128(act ? attp * aw1[oc] : 0.f, sm), 0.f);
    float a1 = fmaxf(redsum128(act ? attp * aw1[OC + oc] : 0.f, sm), 0.f);

    float l[3], mx = -1e30f;
    #pragma unroll
    for (int br = 0; br < 3; br++) {
        l[br] = act ? (a0 * aw2[(br * OC + oc) * 2] + a1 * aw2[(br * OC + oc) * 2 + 1])
                    : -1e30f;
        mx = fmaxf(mx, l[br]);
    }
    float gm = redmax128(mx, sm);
    float e[3], le = 0.f;
    #pragma unroll
    for (int br = 0; br < 3; br++) { e[br] = expf(l[br] - gm); le += e[br]; }
    float S = redsum128(le, sm);
    if (act) {
        #pragma unroll
        for (int br = 0; br < 3; br++)
            g_scale[(br * BSZ + b) * OC + oc] = seg[br] * e[br] / S;
    }
}

// ---------------- kernel 2b: conv recompute + gate + relu -> fp16 ----------------
__global__ void __launch_bounds__(384) conv3_fused(
    const float* __restrict__ f1, const float* __restrict__ f2,
    const float* __restrict__ f3, const int* __restrict__ rel,
    const float* __restrict__ bn0g, const float* __restrict__ bn0b)
{
    __shared__ float xs[HW];
    __shared__ float fs[OC * 9];
    __shared__ float sA[OC], sBt[OC], sS[OC];
    int b = blockIdx.x, brch = blockIdx.y, t = threadIdx.x;

    float N0 = (float)BSZ * HW;
    float mean = g_bn0[0] / N0;
    float var  = g_bn0[1] / N0 - mean * mean;
    float a0 = bn0g[0] * rsqrtf(var + EPSB);
    float b0 = bn0b[0] - mean * a0;

    for (int i = t; i < HW; i += 384) xs[i] = g_x[b * HW + i] * a0 + b0;

    int rb = rel[b];
    int flen = (brch == 1) ? OC * 9 : OC * 5;
    int fstr = (brch == 1) ? 9 : 5;
    const float* fp = (brch == 0 ? f1 : (brch == 1 ? f2 : f3)) + (long)rb * flen;
    for (int i = t; i < flen; i += 384) fs[i] = fp[i];
    if (t < OC) {
        sA[t]  = g_alpha[brch * OC + t];
        sBt[t] = g_beta[brch * OC + t];
        sS[t]  = g_scale[(brch * BSZ + b) * OC + t];
    }
    __syncthreads();

    long obase = (long)b * NFC + (long)brch * (OC * HW);
    for (int i = t; i < OC * HW; i += 384) {
        int oc = i / HW, p = i - oc * HW;
        int h = p / 20, w = p - h * 20;
        float acc = conv_point(xs, &fs[oc * fstr], brch, h, w);
        float v = fmaxf(fmaf(sA[oc], acc, sBt[oc]) * sS[oc], 0.f);
        g_A[obase + i] = __float2half(v);
    }
}

// ---------------- convert kernels ----------------
__global__ void __launch_bounds__(256) convW(const float* __restrict__ w) {
    long i4 = (long)blockIdx.x * 256 + threadIdx.x;   // 22500 blocks x 4 floats
    float4 v = ((const float4*)w)[i4];
    __half2 hh0, hh1;
    hh0.x = __float2half(v.x); hh0.y = __float2half(v.y);
    hh1.x = __float2half(v.z); hh1.y = __float2half(v.w);
    ((__half2*)g_W)[i4 * 2]     = hh0;
    ((__half2*)g_W)[i4 * 2 + 1] = hh1;
}

__global__ void __launch_bounds__(256) convN(const float* __restrict__ nf) {
    long t = (long)blockIdx.x * 256 + threadIdx.x;   // 32500 blocks: 40000*208
    int e = (int)(t / KP2), j = (int)(t - (long)e * KP2);
    float v = (j < DW) ? nf[(long)e * DW + j] : 0.f;
    g_n[t] = __float2half(v);
}

// ---------------- HMMA fp16 GEMM: 128x128 tile, kstep16, 3 stages, occ-2 --------
// 2 planes (A, B); smem stage = 8KB, 3 stages = 24KB.
__device__ __forceinline__ void gemm_hmma(
    const __half* __restrict__ A, long lda,
    const __half* __restrict__ B, long ldb,
    float* __restrict__ C, long ldc, int Nn,
    int m0, int n0, long k0, int nk, const float* __restrict__ bias)
{
    __shared__ __align__(16) char smem[24576];
    unsigned sb = (unsigned)__cvta_generic_to_shared(smem);
    int tid = threadIdx.x, lane = tid & 31, wid = tid >> 5;
    int wm = (wid >> 2) * 64, wn = (wid & 3) * 32;

    float acc[4][4][4];
    #pragma unroll
    for (int i = 0; i < 4; i++)
        #pragma unroll
        for (int j = 0; j < 4; j++)
            #pragma unroll
            for (int k = 0; k < 4; k++) acc[i][j][k] = 0.f;

    auto issue = [&](int stg_, int kb_) {
        unsigned s0_ = sb + (unsigned)stg_ * 8192u;
        long kk_ = k0 + (long)kb_ * 16;
        #pragma unroll
        for (int ii = 0; ii < 2; ii++) {
            int i_ = tid + ii * 256;
            int pl_ = i_ >> 8, r_ = (i_ >> 1) & 127, c_ = i_ & 1;
            unsigned sw_ = s0_ + (unsigned)pl_ * 4096u + (unsigned)r_ * 32u
                         + (unsigned)((c_ ^ ((r_ >> 2) & 1)) * 16);
            if (pl_ == 0) {
                cpa16(sw_, A + (long)(m0 + r_) * lda + kk_ + c_ * 8);
            } else {
                int ok_ = ((n0 + r_) < Nn) ? 16 : 0;
                cpa16z(sw_, B + (long)(n0 + r_) * ldb + kk_ + c_ * 8, ok_);
            }
        }
        asm volatile("cp.async.commit_group;" ::: "memory");
    };

    // per-warp ldmatrix offsets (stage-invariant)
    int cbit = lane >> 4;
    unsigned aoff[4], boff[2];
    #pragma unroll
    for (int mt = 0; mt < 4; mt++) {
        int r = wm + mt * 16 + (lane & 15);
        aoff[mt] = (unsigned)r * 32u + (unsigned)((cbit ^ ((r >> 2) & 1)) * 16);
    }
    #pragma unroll
    for (int j = 0; j < 2; j++) {
        int r = wn + j * 16 + (lane & 15);
        boff[j] = 4096u + (unsigned)r * 32u
                + (unsigned)((cbit ^ ((r >> 2) & 1)) * 16);
    }

    issue(0, 0);
    issue(1, 1);

    for (int kb = 0; kb < nk; kb++) {
        int st = kb % 3;
        if (kb + 1 < nk)
            asm volatile("cp.async.wait_group 1;" ::: "memory");
        else
            asm volatile("cp.async.wait_group 0;" ::: "memory");
        __syncthreads();
        if (kb + 2 < nk) issue((kb + 2) % 3, kb + 2);   // prefetch early

        unsigned s0 = sb + (unsigned)st * 8192u;
        unsigned bh[2][4];
        #pragma unroll
        for (int j = 0; j < 2; j++) ldsm4(bh[j], s0 + boff[j]);
        #pragma unroll
        for (int mt = 0; mt < 4; mt++) {
            unsigned ah[4];
            ldsm4(ah, s0 + aoff[mt]);
            #pragma unroll
            for (int j = 0; j < 2; j++) {
                mma_fp16(acc[mt][2*j],   ah, bh[j][0], bh[j][2]);
                mma_fp16(acc[mt][2*j+1], ah, bh[j][1], bh[j][3]);
            }
        }
        __syncthreads();
    }

    #pragma unroll
    for (int mt = 0; mt < 4; mt++) {
        #pragma unroll
        for (int nt = 0; nt < 4; nt++) {
            int rr = m0 + wm + mt * 16 + (lane >> 2);
            int cc = n0 + wn + nt * 8 + (lane & 3) * 2;
            if (cc < Nn) {
                float bv0 = bias ? bias[cc] : 0.f;
                float bv1 = bias ? bias[cc + 1] : 0.f;
                C[(long)rr * ldc + cc]           = acc[mt][nt][0] + bv0;
                C[(long)rr * ldc + cc + 1]       = acc[mt][nt][1] + bv1;
                C[(long)(rr + 8) * ldc + cc]     = acc[mt][nt][2] + bv0;
                C[(long)(rr + 8) * ldc + cc + 1] = acc[mt][nt][3] + bv1;
            }
        }
    }
}

__global__ void __launch_bounds__(256, 2) gemm1_k() {
    gemm_hmma(g_A, NFC, g_W, NFC,
              g_c1p + (long)blockIdx.z * (BSZ * DW), DW, DW,
              blockIdx.y * 128, blockIdx.x * 128,
              (long)blockIdx.z * CH1, NK1, nullptr);
}

__global__ void __launch_bounds__(256, 2) gemm2_k(
    const float* __restrict__ biasb, float* __restrict__ out) {
    gemm_hmma(g_z, KP2, g_n, KP2,
              out, NENT, NENT,
              blockIdx.y * 128, blockIdx.x * 128, 0, NK2, biasb);
}

// ---------------- kernel 6: split-K reduce + fc bias ----------------
__global__ void __launch_bounds__(256) reduce_c1(const float* __restrict__ fcb) {
    int idx = blockIdx.x * 256 + threadIdx.x;     // 800*256 == 204800
    float s = 0.f;
    #pragma unroll
    for (int z = 0; z < SK1; z++) s += g_c1p[z * (BSZ * DW) + idx];
    g_c1[idx] = s + fcb[idx % DW];
}

// ---------------- kernel 7: BN1d + ReLU -> fp16 (padded to KP2) ----------------
__global__ void __launch_bounds__(256) bn2_relu(
    const float* __restrict__ g2, const float* __restrict__ b2) {
    int d = blockIdx.x, t = threadIdx.x;          // d in [0,KP2)
    if (d >= DW) {
        for (int b = t; b < BSZ; b += 256) g_z[b * KP2 + d] = __float2half(0.f);
        return;
    }
    float s = 0.f, q = 0.f;
    for (int b = t; b < BSZ; b += 256) {
        float v = g_c1[b * DW + d];
        s += v; q += v * v;
    }
    __shared__ float ss[256], sq[256];
    ss[t] = s; sq[t] = q; __syncthreads();
    for (int st = 128; st > 0; st >>= 1) {
        if (t < st) { ss[t] += ss[t + st]; sq[t] += sq[t + st]; }
        __syncthreads();
    }
    float mean = ss[0] / BSZ;
    float var  = sq[0] / BSZ - mean * mean;
    float a = g2[d] * rsqrtf(var + EPSB);
    float bb = b2[d] - mean * a;
    for (int b = t; b < BSZ; b += 256) {
        float v = fmaxf(fmaf(a, g_c1[b * DW + d], bb), 0.f);
        g_z[b * KP2 + d] = __float2half(v);
    }
}

// ---------------- launch ----------------
extern "C" void kernel_launch(void* const* d_in, const int* in_sizes, int n_in,
                              void* d_out, int out_size) {
    const float* n_feats = (const float*)d_in[0];
    const float* r_feats = (const float*)d_in[1];
    const float* filt1   = (const float*)d_in[2];
    const float* filt2   = (const float*)d_in[3];
    const float* filt3   = (const float*)d_in[4];
    const float* bn0_g   = (const float*)d_in[5];
    const float* bn0_b   = (const float*)d_in[6];
    const float* bn1_g   = (const float*)d_in[7];
    const float* bn1_b   = (const float*)d_in[8];
    const float* bn2c_g  = (const float*)d_in[9];
    const float* bn2c_b  = (const float*)d_in[10];
    const float* bn3c_g  = (const float*)d_in[11];
    const float* bn3c_b  = (const float*)d_in[12];
    const float* se1_w1  = (const float*)d_in[13];
    const float* se1_w2  = (const float*)d_in[14];
    const float* se2_w1  = (const float*)d_in[15];
    const float* se2_w2  = (const float*)d_in[16];
    const float* se3_w1  = (const float*)d_in[17];
    const float* se3_w2  = (const float*)d_in[18];
    const float* att_w1  = (const float*)d_in[19];
    const float* att_w2  = (const float*)d_in[20];
    const float* fc_w    = (const float*)d_in[21];
    const float* fc_b    = (const float*)d_in[22];
    const float* bn2_g   = (const float*)d_in[23];
    const float* bn2_b   = (const float*)d_in[24];
    const float* bias_b  = (const float*)d_in[25];
    const int*   sub     = (const int*)d_in[26];
    const int*   rel     = (const int*)d_in[27];

    zero_stats<<<1, 3 * OC>>>();
    convW<<<22500, 256>>>(fc_w);
    convN<<<32500, 256>>>(n_feats);
    gather_bn0<<<BSZ, 128>>>(n_feats, r_feats, sub, rel);
    conv3_stats<<<dim3(BSZ, 3), 384>>>(filt1, filt2, filt3, rel, bn0_g, bn0_b);
    bnaff<<<1, 3 * OC>>>(bn1_g, bn1_b, bn2c_g, bn2c_b, bn3c_g, bn3c_b);
    gates<<<BSZ, 128>>>(se1_w1, se1_w2, se2_w1, se2_w2, se3_w1, se3_w2,
                        att_w1, att_w2);
    conv3_fused<<<dim3(BSZ, 3), 384>>>(filt1, filt2, filt3, rel, bn0_g, bn0_b);
    gemm1_k<<<dim3(2, BSZ / 128, SK1), 256>>>();
    reduce_c1<<<800, 256>>>(fc_b);
    bn2_relu<<<KP2, 256>>>(bn2_g, bn2_b);
    gemm2_k<<<dim3((NENT + 127) / 128, BSZ / 128), 256>>>(bias_b, (float*)d_out);
}